// round 4
// baseline (speedup 1.0000x reference)
#include <cuda_runtime.h>
#include <math.h>
#include <stdint.h>

#define SQ   2048
#define DIM  4096
#define NH   32
#define NKVH 8
#define HD   128
#define KVD  (NKVH*HD)   // 1024

// ---------------- scratch (static device allocations only) ----------------
__device__ float g_xq[(size_t)SQ * DIM];          // 32 MB
__device__ float g_xk[(size_t)SQ * KVD];          // 8 MB
__device__ float g_xv[(size_t)SQ * KVD];          // 8 MB
__device__ float g_att[(size_t)SQ * DIM];         // 32 MB

// ---------------- generic SGEMM (NN), 128x128x8 tiles ----------------
__global__ __launch_bounds__(256)
void sgemm_nn(const float* __restrict__ A, const float* __restrict__ B,
              float* __restrict__ C,
              int K, int lda, int ldb, int ldc)
{
    int m0 = blockIdx.y * 128;
    int n0 = blockIdx.x * 128;

    __shared__ float As[8][128];
    __shared__ float Bs[8][128];

    int tid = threadIdx.x;
    int tx = tid & 15;            // N
    int ty = tid >> 4;            // M
    int arow = tid >> 1;          // 0..127
    int acol = (tid & 1) * 4;     // 0 or 4
    int brow = tid >> 5;          // 0..7
    int bcol = (tid & 31) * 4;    // 0..124

    float acc[8][8];
#pragma unroll
    for (int i = 0; i < 8; i++)
#pragma unroll
        for (int j = 0; j < 8; j++) acc[i][j] = 0.f;

    for (int k0 = 0; k0 < K; k0 += 8) {
        float4 a = *(const float4*)(A + (long)(m0 + arow) * lda + k0 + acol);
        As[acol + 0][arow] = a.x;
        As[acol + 1][arow] = a.y;
        As[acol + 2][arow] = a.z;
        As[acol + 3][arow] = a.w;
        float4 b = *(const float4*)(B + (long)(k0 + brow) * ldb + n0 + bcol);
        *(float4*)(&Bs[brow][bcol]) = b;
        __syncthreads();
#pragma unroll
        for (int kk = 0; kk < 8; kk++) {
            float4 a0 = *(const float4*)(&As[kk][ty * 8]);
            float4 a1 = *(const float4*)(&As[kk][ty * 8 + 4]);
            float4 b0 = *(const float4*)(&Bs[kk][tx * 8]);
            float4 b1 = *(const float4*)(&Bs[kk][tx * 8 + 4]);
            float ar[8] = {a0.x,a0.y,a0.z,a0.w,a1.x,a1.y,a1.z,a1.w};
            float br[8] = {b0.x,b0.y,b0.z,b0.w,b1.x,b1.y,b1.z,b1.w};
#pragma unroll
            for (int i = 0; i < 8; i++)
#pragma unroll
                for (int j = 0; j < 8; j++) acc[i][j] += ar[i] * br[j];
        }
        __syncthreads();
    }

#pragma unroll
    for (int i = 0; i < 8; i++) {
        float* crow = C + (long)(m0 + ty * 8 + i) * ldc + n0 + tx * 8;
        *(float4*)(crow + 0) = make_float4(acc[i][0], acc[i][1], acc[i][2], acc[i][3]);
        *(float4*)(crow + 4) = make_float4(acc[i][4], acc[i][5], acc[i][6], acc[i][7]);
    }
}

// ---------------- RoPE (in place) ----------------
__global__ __launch_bounds__(256)
void rope_kernel(float* __restrict__ t, const float* __restrict__ fc,
                 const float* __restrict__ fs, int nh)
{
    int idx = blockIdx.x * blockDim.x + threadIdx.x;  // over S*nh*64
    int p = idx & 63;
    int rest = idx >> 6;
    int h = rest % nh;
    int s = rest / nh;
    float c  = fc[s * 64 + p];
    float si = fs[s * 64 + p];
    float* base = t + ((size_t)s * nh + h) * HD;
    float te = base[2 * p];
    float to = base[2 * p + 1];
    base[2 * p]     = te * c - to * si;
    base[2 * p + 1] = to * c + te * si;
}

// ---------------- fused flash attention (fp32) ----------------
// grid: (16 q-tiles, 32 heads). 256 threads, 8x8 register blocking.
// Dyn smem: As[8][128] | Bs[8][128] | Vs[8][128] | Ps[128][129]
#define OFF_AS 0
#define OFF_BS 1024
#define OFF_VS 2048
#define OFF_PS 3072
#define FLASH_SMEM ((3072 + 128 * 129) * 4)

__global__ __launch_bounds__(256)
void flash_attn(const float* __restrict__ Qb, const float* __restrict__ Kb,
                const float* __restrict__ Vb, float* __restrict__ Ob)
{
    extern __shared__ float sm[];
    float* As = sm + OFF_AS;   // [8][128]  S-phase A (Q^T chunk)
    float* Bs = sm + OFF_BS;   // [8][128]  S-phase B (K^T chunk)
    float* Vs = sm + OFF_VS;   // [8][128]  V chunk
    float* Ps = sm + OFF_PS;   // [128][129] P transposed [kv][row]

    int h  = blockIdx.y;
    int qt = (gridDim.x - 1) - blockIdx.x;   // heaviest tiles first
    int m0 = qt * 128;

    const float* Q  = Qb + (size_t)h * HD;        // lda DIM
    const float* Kp = Kb + (size_t)(h & 7) * HD;  // ldb KVD
    const float* Vp = Vb + (size_t)(h & 7) * HD;  // ldb KVD

    int tid = threadIdx.x;
    int tx = tid & 15;            // col group
    int ty = tid >> 4;            // row group
    int arow = tid >> 1;
    int acol = (tid & 1) * 4;
    int brow = tid >> 5;
    int bcol = (tid & 31) * 4;

    const float scale = 0.08838834764831845f;  // 1/sqrt(128)

    float O[8][8];
    float mrow[8], lrow[8];
#pragma unroll
    for (int i = 0; i < 8; i++) {
        mrow[i] = -INFINITY;
        lrow[i] = 0.f;
#pragma unroll
        for (int j = 0; j < 8; j++) O[i][j] = 0.f;
    }

    for (int kt = 0; kt <= qt; kt++) {
        int n0 = kt * 128;

        // ---- S = Q K^T for this tile ----
        float acc[8][8];
#pragma unroll
        for (int i = 0; i < 8; i++)
#pragma unroll
            for (int j = 0; j < 8; j++) acc[i][j] = 0.f;

        for (int k0 = 0; k0 < HD; k0 += 8) {
            float4 a = *(const float4*)(Q  + (long)(m0 + arow) * DIM + k0 + acol);
            As[(acol + 0) * 128 + arow] = a.x;
            As[(acol + 1) * 128 + arow] = a.y;
            As[(acol + 2) * 128 + arow] = a.z;
            As[(acol + 3) * 128 + arow] = a.w;
            float4 b = *(const float4*)(Kp + (long)(n0 + arow) * KVD + k0 + acol);
            Bs[(acol + 0) * 128 + arow] = b.x;
            Bs[(acol + 1) * 128 + arow] = b.y;
            Bs[(acol + 2) * 128 + arow] = b.z;
            Bs[(acol + 3) * 128 + arow] = b.w;
            __syncthreads();
#pragma unroll
            for (int kk = 0; kk < 8; kk++) {
                float4 a0 = *(const float4*)(&As[kk * 128 + ty * 8]);
                float4 a1 = *(const float4*)(&As[kk * 128 + ty * 8 + 4]);
                float4 b0 = *(const float4*)(&Bs[kk * 128 + tx * 8]);
                float4 b1 = *(const float4*)(&Bs[kk * 128 + tx * 8 + 4]);
                float ar[8] = {a0.x,a0.y,a0.z,a0.w,a1.x,a1.y,a1.z,a1.w};
                float br[8] = {b0.x,b0.y,b0.z,b0.w,b1.x,b1.y,b1.z,b1.w};
#pragma unroll
                for (int i = 0; i < 8; i++)
#pragma unroll
                    for (int j = 0; j < 8; j++) acc[i][j] += ar[i] * br[j];
            }
            __syncthreads();
        }

        // ---- scale + causal mask (diagonal tile only) ----
        if (kt == qt) {
#pragma unroll
            for (int i = 0; i < 8; i++) {
                int gi = ty * 8 + i;
#pragma unroll
                for (int j = 0; j < 8; j++) {
                    int gj = tx * 8 + j;
                    acc[i][j] = (gj > gi) ? -1e30f : acc[i][j] * scale;
                }
            }
        } else {
#pragma unroll
            for (int i = 0; i < 8; i++)
#pragma unroll
                for (int j = 0; j < 8; j++) acc[i][j] *= scale;
        }

        // ---- online softmax (row groups live in one warp half; shfl over tx) ----
#pragma unroll
        for (int i = 0; i < 8; i++) {
            float tmax = acc[i][0];
#pragma unroll
            for (int j = 1; j < 8; j++) tmax = fmaxf(tmax, acc[i][j]);
#pragma unroll
            for (int o = 8; o; o >>= 1)
                tmax = fmaxf(tmax, __shfl_xor_sync(0xffffffffu, tmax, o));

            float mnew = fmaxf(mrow[i], tmax);
            float alpha = __expf(mrow[i] - mnew);
            mrow[i] = mnew;

            float rsum = 0.f;
#pragma unroll
            for (int j = 0; j < 8; j++) {
                float p = __expf(acc[i][j] - mnew);
                acc[i][j] = p;
                rsum += p;
            }
#pragma unroll
            for (int o = 8; o; o >>= 1)
                rsum += __shfl_xor_sync(0xffffffffu, rsum, o);

            lrow[i] = lrow[i] * alpha + rsum;
#pragma unroll
            for (int j = 0; j < 8; j++) O[i][j] *= alpha;
        }

        // ---- stage P transposed: Ps[kv][row] ----
#pragma unroll
        for (int j = 0; j < 8; j++)
#pragma unroll
            for (int i = 0; i < 8; i++)
                Ps[(tx * 8 + j) * 129 + ty * 8 + i] = acc[i][j];
        __syncthreads();

        // ---- O += P @ V ----
        for (int k0 = 0; k0 < 128; k0 += 8) {
            float4 v = *(const float4*)(Vp + (long)(n0 + k0 + brow) * KVD + bcol);
            *(float4*)(&Vs[brow * 128 + bcol]) = v;
            __syncthreads();
#pragma unroll
            for (int kk = 0; kk < 8; kk++) {
                const float* prow = &Ps[(k0 + kk) * 129 + ty * 8];
                float4 b0 = *(const float4*)(&Vs[kk * 128 + tx * 8]);
                float4 b1 = *(const float4*)(&Vs[kk * 128 + tx * 8 + 4]);
                float br[8] = {b0.x,b0.y,b0.z,b0.w,b1.x,b1.y,b1.z,b1.w};
#pragma unroll
                for (int i = 0; i < 8; i++) {
                    float a = prow[i];
#pragma unroll
                    for (int j = 0; j < 8; j++) O[i][j] += a * br[j];
                }
            }
            __syncthreads();
        }
    }

    // ---- epilogue: O /= l, write [s][h*128+d] ----
#pragma unroll
    for (int i = 0; i < 8; i++) {
        float inv = 1.f / lrow[i];
        float* crow = Ob + (size_t)(m0 + ty * 8 + i) * DIM + h * HD + tx * 8;
        *(float4*)(crow + 0) = make_float4(O[i][0]*inv, O[i][1]*inv, O[i][2]*inv, O[i][3]*inv);
        *(float4*)(crow + 4) = make_float4(O[i][4]*inv, O[i][5]*inv, O[i][6]*inv, O[i][7]*inv);
    }
}

// ---------------- launch ----------------
extern "C" void kernel_launch(void* const* d_in, const int* in_sizes, int n_in,
                              void* d_out, int out_size)
{
    const float* x  = (const float*)d_in[0];
    const float* wq = (const float*)d_in[1];
    const float* wk = (const float*)d_in[2];
    const float* wv = (const float*)d_in[3];
    const float* wo = (const float*)d_in[4];
    const float* fc = (const float*)d_in[5];
    const float* fs = (const float*)d_in[6];
    float* out = (float*)d_out;

    float *pxq, *pxk, *pxv, *patt;
    cudaGetSymbolAddress((void**)&pxq,  g_xq);
    cudaGetSymbolAddress((void**)&pxk,  g_xk);
    cudaGetSymbolAddress((void**)&pxv,  g_xv);
    cudaGetSymbolAddress((void**)&patt, g_att);

    static bool attr_set = false;
    if (!attr_set) {
        cudaFuncSetAttribute(flash_attn, cudaFuncAttributeMaxDynamicSharedMemorySize,
                             FLASH_SMEM);
        attr_set = true;
    }

    // QKV projections
    sgemm_nn<<<dim3(DIM / 128, SQ / 128), 256>>>(x, wq, pxq, DIM, DIM, DIM, DIM);
    sgemm_nn<<<dim3(KVD / 128, SQ / 128), 256>>>(x, wk, pxk, DIM, DIM, KVD, KVD);
    sgemm_nn<<<dim3(KVD / 128, SQ / 128), 256>>>(x, wv, pxv, DIM, DIM, KVD, KVD);

    // RoPE
    rope_kernel<<<(SQ * NH * 64) / 256, 256>>>(pxq, fc, fs, NH);
    rope_kernel<<<(SQ * NKVH * 64) / 256, 256>>>(pxk, fc, fs, NKVH);

    // fused attention (QK^T + softmax + PV), kv head = h % 8
    flash_attn<<<dim3(SQ / 128, NH), 256, FLASH_SMEM>>>(pxq, pxk, pxv, patt);

    // final projection
    sgemm_nn<<<dim3(DIM / 128, SQ / 128), 256>>>(patt, wo, out, DIM, DIM, DIM, DIM);
}

// round 7
// speedup vs baseline: 1.8050x; 1.8050x over previous
#include <cuda_runtime.h>
#include <cuda_bf16.h>
#include <math.h>
#include <stdint.h>

#define SQ   2048
#define DIM  4096
#define NH   32
#define NKVH 8
#define HD   128
#define KVD  (NKVH*HD)   // 1024
#define KTOT 4096        // K of every projection GEMM

// ---------------- scratch (static device allocations only) ----------------
__device__ float g_xq[(size_t)SQ * DIM];
__device__ float g_xk[(size_t)SQ * KVD];
__device__ float g_xv[(size_t)SQ * KVD];
__device__ float g_att[(size_t)SQ * DIM];

__device__ __align__(16) __nv_bfloat16 g_xhi[(size_t)SQ * DIM];
__device__ __align__(16) __nv_bfloat16 g_xlo[(size_t)SQ * DIM];
__device__ __align__(16) __nv_bfloat16 g_atthi[(size_t)SQ * DIM];
__device__ __align__(16) __nv_bfloat16 g_attlo[(size_t)SQ * DIM];
__device__ __align__(16) __nv_bfloat16 g_wqT_hi[(size_t)DIM * DIM];
__device__ __align__(16) __nv_bfloat16 g_wqT_lo[(size_t)DIM * DIM];
__device__ __align__(16) __nv_bfloat16 g_wkT_hi[(size_t)KVD * DIM];
__device__ __align__(16) __nv_bfloat16 g_wkT_lo[(size_t)KVD * DIM];
__device__ __align__(16) __nv_bfloat16 g_wvT_hi[(size_t)KVD * DIM];
__device__ __align__(16) __nv_bfloat16 g_wvT_lo[(size_t)KVD * DIM];
__device__ __align__(16) __nv_bfloat16 g_woT_hi[(size_t)DIM * DIM];
__device__ __align__(16) __nv_bfloat16 g_woT_lo[(size_t)DIM * DIM];

__device__ __forceinline__ uint32_t smem_u32(const void* p) {
    return (uint32_t)__cvta_generic_to_shared(p);
}
#define LDSM_X4(r0, r1, r2, r3, addr)                                          \
    asm volatile("ldmatrix.sync.aligned.m8n8.x4.shared.b16 {%0,%1,%2,%3}, [%4];" \
                 : "=r"(r0), "=r"(r1), "=r"(r2), "=r"(r3) : "r"(addr))
#define MMA16816(c, a, b0_, b1_)                                               \
    asm volatile("mma.sync.aligned.m16n8k16.row.col.f32.bf16.bf16.f32 "        \
                 "{%0,%1,%2,%3}, {%4,%5,%6,%7}, {%8,%9}, {%0,%1,%2,%3};"       \
                 : "+f"((c)[0]), "+f"((c)[1]), "+f"((c)[2]), "+f"((c)[3])      \
                 : "r"((a)[0]), "r"((a)[1]), "r"((a)[2]), "r"((a)[3]),         \
                   "r"(b0_), "r"(b1_))

// ---------------- conversion kernels ----------------
__global__ __launch_bounds__(256)
void split_rows(const float* __restrict__ X, __nv_bfloat16* __restrict__ hi,
                __nv_bfloat16* __restrict__ lo)
{
    size_t i = (size_t)blockIdx.x * 256 + threadIdx.x;
    float v = X[i];
    __nv_bfloat16 h = __float2bfloat16(v);
    hi[i] = h;
    lo[i] = __float2bfloat16(v - __bfloat162float(h));
}

// W [K][N] fp32 row-major -> WT hi/lo [N][K] bf16 (K-major rows)
__global__ __launch_bounds__(256)
void transpose_split(const float* __restrict__ W, __nv_bfloat16* __restrict__ Thi,
                     __nv_bfloat16* __restrict__ Tlo, int K, int N)
{
    __shared__ float tile[32][33];
    int n0 = blockIdx.x * 32, k0 = blockIdx.y * 32;
    int tx = threadIdx.x & 31, ty = threadIdx.x >> 5;  // 32 x 8
#pragma unroll
    for (int j = 0; j < 4; j++)
        tile[ty + j * 8][tx] = W[(size_t)(k0 + ty + j * 8) * N + n0 + tx];
    __syncthreads();
#pragma unroll
    for (int j = 0; j < 4; j++) {
        float v = tile[tx][ty + j * 8];
        __nv_bfloat16 h = __float2bfloat16(v);
        __nv_bfloat16 l = __float2bfloat16(v - __bfloat162float(h));
        size_t o = (size_t)(n0 + ty + j * 8) * K + k0 + tx;
        Thi[o] = h;
        Tlo[o] = l;
    }
}

// ---------------- HMMA (mma.sync) bf16 split-3 GEMM ----------------
// C[M,N] = A * B^T, fp32-equivalent via 3 bf16 passes. A[m][k], B[n][k], K=4096.
// CTA tile 128x128, 8 warps (2x4), warp tile 64x32, K-chunk 32.
#define SPITCH 40   // bf16 elements per smem row (32 data + 8 pad), 80B

__global__ __launch_bounds__(256)
void gemm_bf16_mma(const __nv_bfloat16* __restrict__ Ahi,
                   const __nv_bfloat16* __restrict__ Alo,
                   const __nv_bfloat16* __restrict__ Bhi,
                   const __nv_bfloat16* __restrict__ Blo,
                   float* __restrict__ C, int ldc)
{
    __shared__ __align__(16) __nv_bfloat16 sA[2][128 * SPITCH];
    __shared__ __align__(16) __nv_bfloat16 sB[2][128 * SPITCH];

    int tid = threadIdx.x, wid = tid >> 5, lane = tid & 31;
    int m0 = blockIdx.y * 128, n0 = blockIdx.x * 128;
    int wm = (wid & 1) * 64;        // warp M offset
    int wn = (wid >> 1) * 32;       // warp N offset

    int ldrow = tid >> 2;           // 0..63? no: tid>>2 in 0..63 plus j offset
    int ldq   = (tid & 3) * 8;      // k element offset (uint4 = 8 bf16)

    float acc[4][4][4];
#pragma unroll
    for (int i = 0; i < 4; i++)
#pragma unroll
        for (int j = 0; j < 4; j++)
#pragma unroll
            for (int c = 0; c < 4; c++) acc[i][j][c] = 0.f;

    const int NCH = 384;  // 3 passes x 128 chunks of K=32
    uint4 ra[2], rb[2];

    // prefetch chunk 0 (pass 0: hi*hi)
#pragma unroll
    for (int j = 0; j < 2; j++) {
        int row = ldrow + j * 64;
        ra[j] = *(const uint4*)(Ahi + (size_t)(m0 + row) * KTOT + ldq);
        rb[j] = *(const uint4*)(Bhi + (size_t)(n0 + row) * KTOT + ldq);
    }
#pragma unroll
    for (int j = 0; j < 2; j++) {
        int row = ldrow + j * 64;
        *(uint4*)&sA[0][row * SPITCH + ldq] = ra[j];
        *(uint4*)&sB[0][row * SPITCH + ldq] = rb[j];
    }
    __syncthreads();

    for (int t = 0; t < NCH; t++) {
        // ---- prefetch chunk t+1 ----
        if (t + 1 < NCH) {
            int tn = t + 1;
            int pass = tn >> 7;
            int kk = (tn & 127) * 32;
            const __nv_bfloat16* A = (pass == 2) ? Alo : Ahi;
            const __nv_bfloat16* B = (pass == 1) ? Blo : Bhi;
#pragma unroll
            for (int j = 0; j < 2; j++) {
                int row = ldrow + j * 64;
                ra[j] = *(const uint4*)(A + (size_t)(m0 + row) * KTOT + kk + ldq);
                rb[j] = *(const uint4*)(B + (size_t)(n0 + row) * KTOT + kk + ldq);
            }
        }

        // ---- compute chunk t ----
        {
            int buf = t & 1;
            uint32_t bfr[4][4];
#pragma unroll
            for (int jn = 0; jn < 4; jn++) {
                uint32_t addr = smem_u32(
                    &sB[buf][(wn + jn * 8 + (lane & 7)) * SPITCH + ((lane >> 3) << 3)]);
                LDSM_X4(bfr[jn][0], bfr[jn][1], bfr[jn][2], bfr[jn][3], addr);
            }
#pragma unroll
            for (int ks = 0; ks < 2; ks++) {
                uint32_t afr[4][4];
#pragma unroll
                for (int mi = 0; mi < 4; mi++) {
                    uint32_t addr = smem_u32(
                        &sA[buf][(wm + mi * 16 + (lane & 15)) * SPITCH +
                                 ks * 16 + ((lane >> 4) << 3)]);
                    LDSM_X4(afr[mi][0], afr[mi][1], afr[mi][2], afr[mi][3], addr);
                }
#pragma unroll
                for (int mi = 0; mi < 4; mi++)
#pragma unroll
                    for (int jn = 0; jn < 4; jn++)
                        MMA16816(acc[mi][jn], afr[mi], bfr[jn][2 * ks], bfr[jn][2 * ks + 1]);
            }
        }

        // ---- stage chunk t+1 ----
        if (t + 1 < NCH) {
            int buf = (t + 1) & 1;
#pragma unroll
            for (int j = 0; j < 2; j++) {
                int row = ldrow + j * 64;
                *(uint4*)&sA[buf][row * SPITCH + ldq] = ra[j];
                *(uint4*)&sB[buf][row * SPITCH + ldq] = rb[j];
            }
        }
        __syncthreads();
    }

    // ---- epilogue ----
    int qr = lane >> 2;          // 0..7
    int qc = (lane & 3) * 2;
#pragma unroll
    for (int mi = 0; mi < 4; mi++) {
#pragma unroll
        for (int jn = 0; jn < 4; jn++) {
            int row = m0 + wm + mi * 16 + qr;
            int col = n0 + wn + jn * 8 + qc;
            *(float2*)&C[(size_t)row * ldc + col] =
                make_float2(acc[mi][jn][0], acc[mi][jn][1]);
            *(float2*)&C[(size_t)(row + 8) * ldc + col] =
                make_float2(acc[mi][jn][2], acc[mi][jn][3]);
        }
    }
}

// ---------------- RoPE (in place) ----------------
__global__ __launch_bounds__(256)
void rope_kernel(float* __restrict__ t, const float* __restrict__ fc,
                 const float* __restrict__ fs, int nh)
{
    int idx = blockIdx.x * blockDim.x + threadIdx.x;
    int p = idx & 63;
    int rest = idx >> 6;
    int h = rest % nh;
    int s = rest / nh;
    float c  = fc[s * 64 + p];
    float si = fs[s * 64 + p];
    float* base = t + ((size_t)s * nh + h) * HD;
    float te = base[2 * p];
    float to = base[2 * p + 1];
    base[2 * p]     = te * c - to * si;
    base[2 * p + 1] = to * c + te * si;
}

// ---------------- fused flash attention (fp32) ----------------
#define OFF_AS 0
#define OFF_BS 1024
#define OFF_VS 2048
#define OFF_PS 3072
#define FLASH_SMEM ((3072 + 128 * 129) * 4)

__global__ __launch_bounds__(256)
void flash_attn(const float* __restrict__ Qb, const float* __restrict__ Kb,
                const float* __restrict__ Vb, float* __restrict__ Ob)
{
    extern __shared__ float sm[];
    float* As = sm + OFF_AS;
    float* Bs = sm + OFF_BS;
    float* Vs = sm + OFF_VS;
    float* Ps = sm + OFF_PS;

    int h  = blockIdx.y;
    int qt = (gridDim.x - 1) - blockIdx.x;
    int m0 = qt * 128;

    const float* Q  = Qb + (size_t)h * HD;
    const float* Kp = Kb + (size_t)(h & 7) * HD;
    const float* Vp = Vb + (size_t)(h & 7) * HD;

    int tid = threadIdx.x;
    int tx = tid & 15;
    int ty = tid >> 4;
    int arow = tid >> 1;
    int acol = (tid & 1) * 4;
    int brow = tid >> 5;
    int bcol = (tid & 31) * 4;

    const float scale = 0.08838834764831845f;

    float O[8][8];
    float mrow[8], lrow[8];
#pragma unroll
    for (int i = 0; i < 8; i++) {
        mrow[i] = -INFINITY;
        lrow[i] = 0.f;
#pragma unroll
        for (int j = 0; j < 8; j++) O[i][j] = 0.f;
    }

    for (int kt = 0; kt <= qt; kt++) {
        int n0 = kt * 128;

        float acc[8][8];
#pragma unroll
        for (int i = 0; i < 8; i++)
#pragma unroll
            for (int j = 0; j < 8; j++) acc[i][j] = 0.f;

        for (int k0 = 0; k0 < HD; k0 += 8) {
            float4 a = *(const float4*)(Q  + (long)(m0 + arow) * DIM + k0 + acol);
            As[(acol + 0) * 128 + arow] = a.x;
            As[(acol + 1) * 128 + arow] = a.y;
            As[(acol + 2) * 128 + arow] = a.z;
            As[(acol + 3) * 128 + arow] = a.w;
            float4 b = *(const float4*)(Kp + (long)(n0 + arow) * KVD + k0 + acol);
            Bs[(acol + 0) * 128 + arow] = b.x;
            Bs[(acol + 1) * 128 + arow] = b.y;
            Bs[(acol + 2) * 128 + arow] = b.z;
            Bs[(acol + 3) * 128 + arow] = b.w;
            __syncthreads();
#pragma unroll
            for (int kk = 0; kk < 8; kk++) {
                float4 a0 = *(const float4*)(&As[kk * 128 + ty * 8]);
                float4 a1 = *(const float4*)(&As[kk * 128 + ty * 8 + 4]);
                float4 b0 = *(const float4*)(&Bs[kk * 128 + tx * 8]);
                float4 b1 = *(const float4*)(&Bs[kk * 128 + tx * 8 + 4]);
                float ar[8] = {a0.x,a0.y,a0.z,a0.w,a1.x,a1.y,a1.z,a1.w};
                float br[8] = {b0.x,b0.y,b0.z,b0.w,b1.x,b1.y,b1.z,b1.w};
#pragma unroll
                for (int i = 0; i < 8; i++)
#pragma unroll
                    for (int j = 0; j < 8; j++) acc[i][j] += ar[i] * br[j];
            }
            __syncthreads();
        }

        if (kt == qt) {
#pragma unroll
            for (int i = 0; i < 8; i++) {
                int gi = ty * 8 + i;
#pragma unroll
                for (int j = 0; j < 8; j++) {
                    int gj = tx * 8 + j;
                    acc[i][j] = (gj > gi) ? -1e30f : acc[i][j] * scale;
                }
            }
        } else {
#pragma unroll
            for (int i = 0; i < 8; i++)
#pragma unroll
                for (int j = 0; j < 8; j++) acc[i][j] *= scale;
        }

#pragma unroll
        for (int i = 0; i < 8; i++) {
            float tmax = acc[i][0];
#pragma unroll
            for (int j = 1; j < 8; j++) tmax = fmaxf(tmax, acc[i][j]);
#pragma unroll
            for (int o = 8; o; o >>= 1)
                tmax = fmaxf(tmax, __shfl_xor_sync(0xffffffffu, tmax, o));

            float mnew = fmaxf(mrow[i], tmax);
            float alpha = __expf(mrow[i] - mnew);
            mrow[i] = mnew;

            float rsum = 0.f;
#pragma unroll
            for (int j = 0; j < 8; j++) {
                float p = __expf(acc[i][j] - mnew);
                acc[i][j] = p;
                rsum += p;
            }
#pragma unroll
            for (int o = 8; o; o >>= 1)
                rsum += __shfl_xor_sync(0xffffffffu, rsum, o);

            lrow[i] = lrow[i] * alpha + rsum;
#pragma unroll
            for (int j = 0; j < 8; j++) O[i][j] *= alpha;
        }

#pragma unroll
        for (int j = 0; j < 8; j++)
#pragma unroll
            for (int i = 0; i < 8; i++)
                Ps[(tx * 8 + j) * 129 + ty * 8 + i] = acc[i][j];
        __syncthreads();

        for (int k0 = 0; k0 < 128; k0 += 8) {
            float4 v = *(const float4*)(Vp + (long)(n0 + k0 + brow) * KVD + bcol);
            *(float4*)(&Vs[brow * 128 + bcol]) = v;
            __syncthreads();
#pragma unroll
            for (int kk = 0; kk < 8; kk++) {
                const float* prow = &Ps[(k0 + kk) * 129 + ty * 8];
                float4 b0 = *(const float4*)(&Vs[kk * 128 + tx * 8]);
                float4 b1 = *(const float4*)(&Vs[kk * 128 + tx * 8 + 4]);
                float br[8] = {b0.x,b0.y,b0.z,b0.w,b1.x,b1.y,b1.z,b1.w};
#pragma unroll
                for (int i = 0; i < 8; i++) {
                    float a = prow[i];
#pragma unroll
                    for (int j = 0; j < 8; j++) O[i][j] += a * br[j];
                }
            }
            __syncthreads();
        }
    }

#pragma unroll
    for (int i = 0; i < 8; i++) {
        float inv = 1.f / lrow[i];
        float* crow = Ob + (size_t)(m0 + ty * 8 + i) * DIM + h * HD + tx * 8;
        *(float4*)(crow + 0) = make_float4(O[i][0]*inv, O[i][1]*inv, O[i][2]*inv, O[i][3]*inv);
        *(float4*)(crow + 4) = make_float4(O[i][4]*inv, O[i][5]*inv, O[i][6]*inv, O[i][7]*inv);
    }
}

// ---------------- launch ----------------
extern "C" void kernel_launch(void* const* d_in, const int* in_sizes, int n_in,
                              void* d_out, int out_size)
{
    const float* x  = (const float*)d_in[0];
    const float* wq = (const float*)d_in[1];
    const float* wk = (const float*)d_in[2];
    const float* wv = (const float*)d_in[3];
    const float* wo = (const float*)d_in[4];
    const float* fc = (const float*)d_in[5];
    const float* fs = (const float*)d_in[6];
    float* out = (float*)d_out;

    float *pxq, *pxk, *pxv, *patt;
    __nv_bfloat16 *pxhi, *pxlo, *pahi, *palo;
    __nv_bfloat16 *pwqh, *pwql, *pwkh, *pwkl, *pwvh, *pwvl, *pwoh, *pwol;
    cudaGetSymbolAddress((void**)&pxq,  g_xq);
    cudaGetSymbolAddress((void**)&pxk,  g_xk);
    cudaGetSymbolAddress((void**)&pxv,  g_xv);
    cudaGetSymbolAddress((void**)&patt, g_att);
    cudaGetSymbolAddress((void**)&pxhi, g_xhi);
    cudaGetSymbolAddress((void**)&pxlo, g_xlo);
    cudaGetSymbolAddress((void**)&pahi, g_atthi);
    cudaGetSymbolAddress((void**)&palo, g_attlo);
    cudaGetSymbolAddress((void**)&pwqh, g_wqT_hi);
    cudaGetSymbolAddress((void**)&pwql, g_wqT_lo);
    cudaGetSymbolAddress((void**)&pwkh, g_wkT_hi);
    cudaGetSymbolAddress((void**)&pwkl, g_wkT_lo);
    cudaGetSymbolAddress((void**)&pwvh, g_wvT_hi);
    cudaGetSymbolAddress((void**)&pwvl, g_wvT_lo);
    cudaGetSymbolAddress((void**)&pwoh, g_woT_hi);
    cudaGetSymbolAddress((void**)&pwol, g_woT_lo);

    static bool attr_set = false;
    if (!attr_set) {
        cudaFuncSetAttribute(flash_attn, cudaFuncAttributeMaxDynamicSharedMemorySize,
                             FLASH_SMEM);
        attr_set = true;
    }

    // ---- conversions ----
    split_rows<<<(SQ * DIM) / 256, 256>>>(x, pxhi, pxlo);
    transpose_split<<<dim3(DIM / 32, DIM / 32), 256>>>(wq, pwqh, pwql, DIM, DIM);
    transpose_split<<<dim3(KVD / 32, DIM / 32), 256>>>(wk, pwkh, pwkl, DIM, KVD);
    transpose_split<<<dim3(KVD / 32, DIM / 32), 256>>>(wv, pwvh, pwvl, DIM, KVD);
    transpose_split<<<dim3(DIM / 32, DIM / 32), 256>>>(wo, pwoh, pwol, DIM, DIM);

    // ---- QKV projections via mma.sync bf16 split-3 ----
    gemm_bf16_mma<<<dim3(DIM / 128, SQ / 128), 256>>>(pxhi, pxlo, pwqh, pwql, pxq, DIM);
    gemm_bf16_mma<<<dim3(KVD / 128, SQ / 128), 256>>>(pxhi, pxlo, pwkh, pwkl, pxk, KVD);
    gemm_bf16_mma<<<dim3(KVD / 128, SQ / 128), 256>>>(pxhi, pxlo, pwvh, pwvl, pxv, KVD);

    // ---- RoPE ----
    rope_kernel<<<(SQ * NH * 64) / 256, 256>>>(pxq, fc, fs, NH);
    rope_kernel<<<(SQ * NKVH * 64) / 256, 256>>>(pxk, fc, fs, NKVH);

    // ---- fused attention (fp32) ----
    flash_attn<<<dim3(SQ / 128, NH), 256, FLASH_SMEM>>>(pxq, pxk, pxv, patt);

    // ---- output projection via mma.sync bf16 split-3 ----
    split_rows<<<(SQ * DIM) / 256, 256>>>(patt, pahi, palo);
    gemm_bf16_mma<<<dim3(DIM / 128, SQ / 128), 256>>>(pahi, palo, pwoh, pwol, out, DIM);
}

// round 8
// speedup vs baseline: 2.2219x; 1.2310x over previous
#include <cuda_runtime.h>
#include <cuda_bf16.h>
#include <math.h>
#include <stdint.h>

#define SQ   2048
#define DIM  4096
#define NH   32
#define NKVH 8
#define HD   128
#define KVD  (NKVH*HD)   // 1024
#define KTOT 4096        // K of every projection GEMM

// ---------------- scratch (static device allocations only) ----------------
__device__ float g_xq[(size_t)SQ * DIM];
__device__ float g_xk[(size_t)SQ * KVD];
__device__ float g_xv[(size_t)SQ * KVD];
__device__ float g_att[(size_t)SQ * DIM];

__device__ __align__(16) __nv_bfloat16 g_xhi[(size_t)SQ * DIM];
__device__ __align__(16) __nv_bfloat16 g_xlo[(size_t)SQ * DIM];
__device__ __align__(16) __nv_bfloat16 g_atthi[(size_t)SQ * DIM];
__device__ __align__(16) __nv_bfloat16 g_attlo[(size_t)SQ * DIM];
__device__ __align__(16) __nv_bfloat16 g_qhi[(size_t)SQ * DIM];
__device__ __align__(16) __nv_bfloat16 g_qlo[(size_t)SQ * DIM];
__device__ __align__(16) __nv_bfloat16 g_khi[(size_t)SQ * KVD];
__device__ __align__(16) __nv_bfloat16 g_klo[(size_t)SQ * KVD];
__device__ __align__(16) __nv_bfloat16 g_vhi[(size_t)SQ * KVD];
__device__ __align__(16) __nv_bfloat16 g_vlo[(size_t)SQ * KVD];
__device__ __align__(16) __nv_bfloat16 g_wqT_hi[(size_t)DIM * DIM];
__device__ __align__(16) __nv_bfloat16 g_wqT_lo[(size_t)DIM * DIM];
__device__ __align__(16) __nv_bfloat16 g_wkT_hi[(size_t)KVD * DIM];
__device__ __align__(16) __nv_bfloat16 g_wkT_lo[(size_t)KVD * DIM];
__device__ __align__(16) __nv_bfloat16 g_wvT_hi[(size_t)KVD * DIM];
__device__ __align__(16) __nv_bfloat16 g_wvT_lo[(size_t)KVD * DIM];
__device__ __align__(16) __nv_bfloat16 g_woT_hi[(size_t)DIM * DIM];
__device__ __align__(16) __nv_bfloat16 g_woT_lo[(size_t)DIM * DIM];

__device__ __forceinline__ uint32_t smem_u32(const void* p) {
    return (uint32_t)__cvta_generic_to_shared(p);
}
#define LDSM_X4(r0, r1, r2, r3, addr)                                          \
    asm volatile("ldmatrix.sync.aligned.m8n8.x4.shared.b16 {%0,%1,%2,%3}, [%4];" \
                 : "=r"(r0), "=r"(r1), "=r"(r2), "=r"(r3) : "r"(addr))
#define LDSM_X4_T(r0, r1, r2, r3, addr)                                        \
    asm volatile("ldmatrix.sync.aligned.m8n8.x4.trans.shared.b16 {%0,%1,%2,%3}, [%4];" \
                 : "=r"(r0), "=r"(r1), "=r"(r2), "=r"(r3) : "r"(addr))
#define MMA16816(c, a, b0_, b1_)                                               \
    asm volatile("mma.sync.aligned.m16n8k16.row.col.f32.bf16.bf16.f32 "        \
                 "{%0,%1,%2,%3}, {%4,%5,%6,%7}, {%8,%9}, {%0,%1,%2,%3};"       \
                 : "+f"((c)[0]), "+f"((c)[1]), "+f"((c)[2]), "+f"((c)[3])      \
                 : "r"((a)[0]), "r"((a)[1]), "r"((a)[2]), "r"((a)[3]),         \
                   "r"(b0_), "r"(b1_))
// pack two fp32 -> bf16x2 reg: lower = lo, upper = hi
__device__ __forceinline__ uint32_t pack_bf16x2(float lo, float hi) {
    uint32_t r;
    asm("cvt.rn.bf16x2.f32 %0, %1, %2;" : "=r"(r) : "f"(hi), "f"(lo));
    return r;
}
// FFMA-only exp (avoids MUFU bottleneck); rel err ~1.5e-4
__device__ __forceinline__ float exp_fast(float x) {
    float t = fmaxf(x * 1.4426950408889634f, -126.0f);
    float fi = floorf(t);
    float f = t - fi;
    float p = fmaf(f, 0.0013333558f, 0.0096181291f);
    p = fmaf(f, p, 0.0555041087f);
    p = fmaf(f, p, 0.2402265069f);
    p = fmaf(f, p, 0.6931471806f);
    p = fmaf(f, p, 1.0f);
    int i = (int)fi;
    return __int_as_float((uint32_t)(i + 127) << 23) * p;
}

// ---------------- conversion kernels ----------------
__global__ __launch_bounds__(256)
void split_rows(const float* __restrict__ X, __nv_bfloat16* __restrict__ hi,
                __nv_bfloat16* __restrict__ lo)
{
    size_t i = (size_t)blockIdx.x * 256 + threadIdx.x;
    float v = X[i];
    __nv_bfloat16 h = __float2bfloat16(v);
    hi[i] = h;
    lo[i] = __float2bfloat16(v - __bfloat162float(h));
}

__global__ __launch_bounds__(256)
void transpose_split(const float* __restrict__ W, __nv_bfloat16* __restrict__ Thi,
                     __nv_bfloat16* __restrict__ Tlo, int K, int N)
{
    __shared__ float tile[32][33];
    int n0 = blockIdx.x * 32, k0 = blockIdx.y * 32;
    int tx = threadIdx.x & 31, ty = threadIdx.x >> 5;
#pragma unroll
    for (int j = 0; j < 4; j++)
        tile[ty + j * 8][tx] = W[(size_t)(k0 + ty + j * 8) * N + n0 + tx];
    __syncthreads();
#pragma unroll
    for (int j = 0; j < 4; j++) {
        float v = tile[tx][ty + j * 8];
        __nv_bfloat16 h = __float2bfloat16(v);
        __nv_bfloat16 l = __float2bfloat16(v - __bfloat162float(h));
        size_t o = (size_t)(n0 + ty + j * 8) * K + k0 + tx;
        Thi[o] = h;
        Tlo[o] = l;
    }
}

// rope in fp32, write bf16 hi/lo
__global__ __launch_bounds__(256)
void rope_split(const float* __restrict__ t, const float* __restrict__ fc,
                const float* __restrict__ fs, __nv_bfloat16* __restrict__ hi,
                __nv_bfloat16* __restrict__ lo, int nh)
{
    int idx = blockIdx.x * blockDim.x + threadIdx.x;
    int p = idx & 63;
    int rest = idx >> 6;
    int h = rest % nh;
    int s = rest / nh;
    float c  = fc[s * 64 + p];
    float si = fs[s * 64 + p];
    const float* base = t + ((size_t)s * nh + h) * HD;
    float te = base[2 * p];
    float to = base[2 * p + 1];
    float e = te * c - to * si;
    float o = to * c + te * si;
    size_t off = ((size_t)s * nh + h) * HD + 2 * p;
    __nv_bfloat16 eh = __float2bfloat16(e);
    __nv_bfloat16 oh = __float2bfloat16(o);
    hi[off] = eh;
    hi[off + 1] = oh;
    lo[off] = __float2bfloat16(e - __bfloat162float(eh));
    lo[off + 1] = __float2bfloat16(o - __bfloat162float(oh));
}

// ---------------- HMMA (mma.sync) bf16 split-3 GEMM (projections) ----------------
#define SPITCH 40

__global__ __launch_bounds__(256)
void gemm_bf16_mma(const __nv_bfloat16* __restrict__ Ahi,
                   const __nv_bfloat16* __restrict__ Alo,
                   const __nv_bfloat16* __restrict__ Bhi,
                   const __nv_bfloat16* __restrict__ Blo,
                   float* __restrict__ C, int ldc)
{
    __shared__ __align__(16) __nv_bfloat16 sA[2][128 * SPITCH];
    __shared__ __align__(16) __nv_bfloat16 sB[2][128 * SPITCH];

    int tid = threadIdx.x, wid = tid >> 5, lane = tid & 31;
    int m0 = blockIdx.y * 128, n0 = blockIdx.x * 128;
    int wm = (wid & 1) * 64;
    int wn = (wid >> 1) * 32;
    int ldrow = tid >> 2;
    int ldq   = (tid & 3) * 8;

    float acc[4][4][4];
#pragma unroll
    for (int i = 0; i < 4; i++)
#pragma unroll
        for (int j = 0; j < 4; j++)
#pragma unroll
            for (int c = 0; c < 4; c++) acc[i][j][c] = 0.f;

    const int NCH = 384;
    uint4 ra[2], rb[2];

#pragma unroll
    for (int j = 0; j < 2; j++) {
        int row = ldrow + j * 64;
        ra[j] = *(const uint4*)(Ahi + (size_t)(m0 + row) * KTOT + ldq);
        rb[j] = *(const uint4*)(Bhi + (size_t)(n0 + row) * KTOT + ldq);
    }
#pragma unroll
    for (int j = 0; j < 2; j++) {
        int row = ldrow + j * 64;
        *(uint4*)&sA[0][row * SPITCH + ldq] = ra[j];
        *(uint4*)&sB[0][row * SPITCH + ldq] = rb[j];
    }
    __syncthreads();

    for (int t = 0; t < NCH; t++) {
        if (t + 1 < NCH) {
            int tn = t + 1;
            int pass = tn >> 7;
            int kk = (tn & 127) * 32;
            const __nv_bfloat16* A = (pass == 2) ? Alo : Ahi;
            const __nv_bfloat16* B = (pass == 1) ? Blo : Bhi;
#pragma unroll
            for (int j = 0; j < 2; j++) {
                int row = ldrow + j * 64;
                ra[j] = *(const uint4*)(A + (size_t)(m0 + row) * KTOT + kk + ldq);
                rb[j] = *(const uint4*)(B + (size_t)(n0 + row) * KTOT + kk + ldq);
            }
        }
        {
            int buf = t & 1;
            uint32_t bfr[4][4];
#pragma unroll
            for (int jn = 0; jn < 4; jn++) {
                uint32_t addr = smem_u32(
                    &sB[buf][(wn + jn * 8 + (lane & 7)) * SPITCH + ((lane >> 3) << 3)]);
                LDSM_X4(bfr[jn][0], bfr[jn][1], bfr[jn][2], bfr[jn][3], addr);
            }
#pragma unroll
            for (int ks = 0; ks < 2; ks++) {
                uint32_t afr[4][4];
#pragma unroll
                for (int mi = 0; mi < 4; mi++) {
                    uint32_t addr = smem_u32(
                        &sA[buf][(wm + mi * 16 + (lane & 15)) * SPITCH +
                                 ks * 16 + ((lane >> 4) << 3)]);
                    LDSM_X4(afr[mi][0], afr[mi][1], afr[mi][2], afr[mi][3], addr);
                }
#pragma unroll
                for (int mi = 0; mi < 4; mi++)
#pragma unroll
                    for (int jn = 0; jn < 4; jn++)
                        MMA16816(acc[mi][jn], afr[mi], bfr[jn][2 * ks], bfr[jn][2 * ks + 1]);
            }
        }
        if (t + 1 < NCH) {
            int buf = (t + 1) & 1;
#pragma unroll
            for (int j = 0; j < 2; j++) {
                int row = ldrow + j * 64;
                *(uint4*)&sA[buf][row * SPITCH + ldq] = ra[j];
                *(uint4*)&sB[buf][row * SPITCH + ldq] = rb[j];
            }
        }
        __syncthreads();
    }

    int qr = lane >> 2;
    int qc = (lane & 3) * 2;
#pragma unroll
    for (int mi = 0; mi < 4; mi++) {
#pragma unroll
        for (int jn = 0; jn < 4; jn++) {
            int row = m0 + wm + mi * 16 + qr;
            int col = n0 + wn + jn * 8 + qc;
            *(float2*)&C[(size_t)row * ldc + col] =
                make_float2(acc[mi][jn][0], acc[mi][jn][1]);
            *(float2*)&C[(size_t)(row + 8) * ldc + col] =
                make_float2(acc[mi][jn][2], acc[mi][jn][3]);
        }
    }
}

// ---------------- HMMA flash attention (bf16 split-3, fp32 softmax) ----------------
#define PIT 136                         // bf16 elems per smem row (128+8 pad)
#define TBYTES (128 * PIT * 2)          // 34816 B per tile buffer
#define FLASH_SMEM (6 * TBYTES)         // Qhi Qlo Khi Klo Vhi Vlo = 208896 B

__global__ __launch_bounds__(256, 1)
void flash_mma(const __nv_bfloat16* __restrict__ Qhi, const __nv_bfloat16* __restrict__ Qlo,
               const __nv_bfloat16* __restrict__ Khi, const __nv_bfloat16* __restrict__ Klo,
               const __nv_bfloat16* __restrict__ Vhi, const __nv_bfloat16* __restrict__ Vlo,
               float* __restrict__ Ob)
{
    extern __shared__ __nv_bfloat16 smf[];
    __nv_bfloat16* sQh = smf;
    __nv_bfloat16* sQl = smf + 128 * PIT;
    __nv_bfloat16* sKh = smf + 2 * 128 * PIT;
    __nv_bfloat16* sKl = smf + 3 * 128 * PIT;
    __nv_bfloat16* sVh = smf + 4 * 128 * PIT;
    __nv_bfloat16* sVl = smf + 5 * 128 * PIT;

    int h  = blockIdx.y;
    int qt = (gridDim.x - 1) - blockIdx.x;   // heaviest first
    int m0 = qt * 128;
    int kvh = h & 7;

    int tid = threadIdx.x, w = tid >> 5, lane = tid & 31;
    int gr = lane >> 2;            // row within 8
    int qc = (lane & 3) * 2;       // col pair

    // ---- stage Q tile (hi/lo) ----
#pragma unroll
    for (int it = 0; it < 8; it++) {
        int idx = it * 256 + tid;
        int row = idx >> 4, c4 = idx & 15;
        *(uint4*)&sQh[row * PIT + c4 * 8] =
            *(const uint4*)(Qhi + (size_t)(m0 + row) * DIM + h * HD + c4 * 8);
        *(uint4*)&sQl[row * PIT + c4 * 8] =
            *(const uint4*)(Qlo + (size_t)(m0 + row) * DIM + h * HD + c4 * 8);
    }
    __syncthreads();

    float o[16][4];
#pragma unroll
    for (int j = 0; j < 16; j++)
#pragma unroll
        for (int c = 0; c < 4; c++) o[j][c] = 0.f;
    float mrow[2] = {-INFINITY, -INFINITY};
    float lrow[2] = {0.f, 0.f};

    const float scale = 0.08838834764831845f;

    for (int kt = 0; kt <= qt; kt++) {
        int n0 = kt * 128;

        // ---- stage K,V tiles ----
#pragma unroll
        for (int it = 0; it < 8; it++) {
            int idx = it * 256 + tid;
            int row = idx >> 4, c4 = idx & 15;
            size_t g = (size_t)(n0 + row) * KVD + kvh * HD + c4 * 8;
            *(uint4*)&sKh[row * PIT + c4 * 8] = *(const uint4*)(Khi + g);
            *(uint4*)&sKl[row * PIT + c4 * 8] = *(const uint4*)(Klo + g);
            *(uint4*)&sVh[row * PIT + c4 * 8] = *(const uint4*)(Vhi + g);
            *(uint4*)&sVl[row * PIT + c4 * 8] = *(const uint4*)(Vlo + g);
        }
        __syncthreads();

        // ---- S = Q K^T (split-3) ----
        float s[16][4];
#pragma unroll
        for (int j = 0; j < 16; j++)
#pragma unroll
            for (int c = 0; c < 4; c++) s[j][c] = 0.f;

#pragma unroll
        for (int pass = 0; pass < 3; pass++) {
            const __nv_bfloat16* As = (pass == 2) ? sQl : sQh;
            const __nv_bfloat16* Bs = (pass == 1) ? sKl : sKh;
#pragma unroll
            for (int g = 0; g < 4; g++) {
                uint32_t a0[4], a1[4];
                uint32_t addrA = smem_u32(
                    &As[(w * 16 + (lane & 15)) * PIT + g * 32 + ((lane >> 4) << 3)]);
                LDSM_X4(a0[0], a0[1], a0[2], a0[3], addrA);
                LDSM_X4(a1[0], a1[1], a1[2], a1[3], addrA + 32);
#pragma unroll
                for (int jn = 0; jn < 16; jn++) {
                    uint32_t b0, b1, b2, b3;
                    uint32_t addrB = smem_u32(
                        &Bs[(jn * 8 + (lane & 7)) * PIT + g * 32 + ((lane >> 3) << 3)]);
                    LDSM_X4(b0, b1, b2, b3, addrB);
                    MMA16816(s[jn], a0, b0, b1);
                    MMA16816(s[jn], a1, b2, b3);
                }
            }
        }

        // ---- scale + causal mask ----
        if (kt == qt) {
#pragma unroll
            for (int jn = 0; jn < 16; jn++) {
                int c0 = jn * 8 + qc;
                int r0 = w * 16 + gr;
                s[jn][0] = (c0     > r0    ) ? -1e30f : s[jn][0] * scale;
                s[jn][1] = (c0 + 1 > r0    ) ? -1e30f : s[jn][1] * scale;
                s[jn][2] = (c0     > r0 + 8) ? -1e30f : s[jn][2] * scale;
                s[jn][3] = (c0 + 1 > r0 + 8) ? -1e30f : s[jn][3] * scale;
            }
        } else {
#pragma unroll
            for (int jn = 0; jn < 16; jn++)
#pragma unroll
                for (int c = 0; c < 4; c++) s[jn][c] *= scale;
        }

        // ---- online softmax (per half: rows gr, gr+8) ----
#pragma unroll
        for (int half = 0; half < 2; half++) {
            int b = half * 2;
            float tmax = s[0][b];
#pragma unroll
            for (int jn = 0; jn < 16; jn++)
                tmax = fmaxf(tmax, fmaxf(s[jn][b], s[jn][b + 1]));
            tmax = fmaxf(tmax, __shfl_xor_sync(0xffffffffu, tmax, 1));
            tmax = fmaxf(tmax, __shfl_xor_sync(0xffffffffu, tmax, 2));

            float mnew = fmaxf(mrow[half], tmax);
            float alpha = exp_fast(mrow[half] - mnew);
            mrow[half] = mnew;

            float rsum = 0.f;
#pragma unroll
            for (int jn = 0; jn < 16; jn++) {
                float p0 = exp_fast(s[jn][b] - mnew);
                float p1 = exp_fast(s[jn][b + 1] - mnew);
                s[jn][b] = p0;
                s[jn][b + 1] = p1;
                rsum += p0 + p1;
            }
            rsum += __shfl_xor_sync(0xffffffffu, rsum, 1);
            rsum += __shfl_xor_sync(0xffffffffu, rsum, 2);

            lrow[half] = lrow[half] * alpha + rsum;
#pragma unroll
            for (int jn = 0; jn < 16; jn++) {
                o[jn][b]     *= alpha;
                o[jn][b + 1] *= alpha;
            }
        }

        // ---- P -> bf16 hi/lo A-fragments (register-only, FA2 layout trick) ----
        uint32_t ph[8][4], pl[8][4];
#pragma unroll
        for (int ks = 0; ks < 8; ks++) {
#pragma unroll
            for (int q = 0; q < 4; q++) {
                int jn = 2 * ks + (q >> 1);
                int c  = (q & 1) * 2;
                float f0 = s[jn][c], f1 = s[jn][c + 1];
                uint32_t hp = pack_bf16x2(f0, f1);
                ph[ks][q] = hp;
                float h0 = __uint_as_float(hp << 16);
                float h1 = __uint_as_float(hp & 0xffff0000u);
                pl[ks][q] = pack_bf16x2(f0 - h0, f1 - h1);
            }
        }

        // ---- O += P V (split-3), V via trans ldmatrix ----
#pragma unroll
        for (int pass = 0; pass < 3; pass++) {
            const uint32_t (*A)[4] = (pass == 2) ? pl : ph;
            const __nv_bfloat16* Vs = (pass == 1) ? sVl : sVh;
#pragma unroll
            for (int ks = 0; ks < 8; ks++) {
#pragma unroll
                for (int jp = 0; jp < 8; jp++) {
                    uint32_t b0, b1, b2, b3;
                    uint32_t addr = smem_u32(
                        &Vs[(ks * 16 + (lane & 7) + ((lane >> 3) & 1) * 8) * PIT +
                            jp * 16 + ((lane >> 4) << 3)]);
                    LDSM_X4_T(b0, b1, b2, b3, addr);
                    MMA16816(o[2 * jp],     A[ks], b0, b1);
                    MMA16816(o[2 * jp + 1], A[ks], b2, b3);
                }
            }
        }
        __syncthreads();
    }

    // ---- epilogue ----
    float inv0 = 1.f / lrow[0], inv1 = 1.f / lrow[1];
    int row0 = m0 + w * 16 + gr;
#pragma unroll
    for (int jn = 0; jn < 16; jn++) {
        int col = h * HD + jn * 8 + qc;
        *(float2*)&Ob[(size_t)row0 * DIM + col] =
            make_float2(o[jn][0] * inv0, o[jn][1] * inv0);
        *(float2*)&Ob[(size_t)(row0 + 8) * DIM + col] =
            make_float2(o[jn][2] * inv1, o[jn][3] * inv1);
    }
}

// ---------------- launch ----------------
extern "C" void kernel_launch(void* const* d_in, const int* in_sizes, int n_in,
                              void* d_out, int out_size)
{
    const float* x  = (const float*)d_in[0];
    const float* wq = (const float*)d_in[1];
    const float* wk = (const float*)d_in[2];
    const float* wv = (const float*)d_in[3];
    const float* wo = (const float*)d_in[4];
    const float* fc = (const float*)d_in[5];
    const float* fs = (const float*)d_in[6];
    float* out = (float*)d_out;

    float *pxq, *pxk, *pxv, *patt;
    __nv_bfloat16 *pxhi, *pxlo, *pahi, *palo;
    __nv_bfloat16 *pqh, *pql, *pkh, *pkl, *pvh, *pvl;
    __nv_bfloat16 *pwqh, *pwql, *pwkh, *pwkl, *pwvh, *pwvl, *pwoh, *pwol;
    cudaGetSymbolAddress((void**)&pxq,  g_xq);
    cudaGetSymbolAddress((void**)&pxk,  g_xk);
    cudaGetSymbolAddress((void**)&pxv,  g_xv);
    cudaGetSymbolAddress((void**)&patt, g_att);
    cudaGetSymbolAddress((void**)&pxhi, g_xhi);
    cudaGetSymbolAddress((void**)&pxlo, g_xlo);
    cudaGetSymbolAddress((void**)&pahi, g_atthi);
    cudaGetSymbolAddress((void**)&palo, g_attlo);
    cudaGetSymbolAddress((void**)&pqh,  g_qhi);
    cudaGetSymbolAddress((void**)&pql,  g_qlo);
    cudaGetSymbolAddress((void**)&pkh,  g_khi);
    cudaGetSymbolAddress((void**)&pkl,  g_klo);
    cudaGetSymbolAddress((void**)&pvh,  g_vhi);
    cudaGetSymbolAddress((void**)&pvl,  g_vlo);
    cudaGetSymbolAddress((void**)&pwqh, g_wqT_hi);
    cudaGetSymbolAddress((void**)&pwql, g_wqT_lo);
    cudaGetSymbolAddress((void**)&pwkh, g_wkT_hi);
    cudaGetSymbolAddress((void**)&pwkl, g_wkT_lo);
    cudaGetSymbolAddress((void**)&pwvh, g_wvT_hi);
    cudaGetSymbolAddress((void**)&pwvl, g_wvT_lo);
    cudaGetSymbolAddress((void**)&pwoh, g_woT_hi);
    cudaGetSymbolAddress((void**)&pwol, g_woT_lo);

    static bool attr_set = false;
    if (!attr_set) {
        cudaFuncSetAttribute(flash_mma, cudaFuncAttributeMaxDynamicSharedMemorySize,
                             FLASH_SMEM);
        attr_set = true;
    }

    // ---- conversions ----
    split_rows<<<(SQ * DIM) / 256, 256>>>(x, pxhi, pxlo);
    transpose_split<<<dim3(DIM / 32, DIM / 32), 256>>>(wq, pwqh, pwql, DIM, DIM);
    transpose_split<<<dim3(KVD / 32, DIM / 32), 256>>>(wk, pwkh, pwkl, DIM, KVD);
    transpose_split<<<dim3(KVD / 32, DIM / 32), 256>>>(wv, pwvh, pwvl, DIM, KVD);
    transpose_split<<<dim3(DIM / 32, DIM / 32), 256>>>(wo, pwoh, pwol, DIM, DIM);

    // ---- QKV projections (mma.sync split-3) ----
    gemm_bf16_mma<<<dim3(DIM / 128, SQ / 128), 256>>>(pxhi, pxlo, pwqh, pwql, pxq, DIM);
    gemm_bf16_mma<<<dim3(KVD / 128, SQ / 128), 256>>>(pxhi, pxlo, pwkh, pwkl, pxk, KVD);
    gemm_bf16_mma<<<dim3(KVD / 128, SQ / 128), 256>>>(pxhi, pxlo, pwvh, pwvl, pxv, KVD);

    // ---- RoPE -> bf16 hi/lo; V split ----
    rope_split<<<(SQ * NH * 64) / 256, 256>>>(pxq, fc, fs, pqh, pql, NH);
    rope_split<<<(SQ * NKVH * 64) / 256, 256>>>(pxk, fc, fs, pkh, pkl, NKVH);
    split_rows<<<(SQ * KVD) / 256, 256>>>(pxv, pvh, pvl);

    // ---- fused attention on HMMA ----
    flash_mma<<<dim3(SQ / 128, NH), 256, FLASH_SMEM>>>(pqh, pql, pkh, pkl, pvh, pvl, patt);

    // ---- output projection (mma.sync split-3) ----
    split_rows<<<(SQ * DIM) / 256, 256>>>(patt, pahi, palo);
    gemm_bf16_mma<<<dim3(DIM / 128, SQ / 128), 256>>>(pahi, palo, pwoh, pwol, out, DIM);
}

// round 10
// speedup vs baseline: 2.7167x; 1.2227x over previous
#include <cuda_runtime.h>
#include <cuda_bf16.h>
#include <math.h>
#include <stdint.h>

#define SQ   2048
#define DIM  4096
#define NH   32
#define NKVH 8
#define HD   128
#define KVD  (NKVH*HD)   // 1024
#define KTOT 4096

// ---------------- scratch (static device allocations only) ----------------
__device__ float g_xq[(size_t)SQ * DIM];
__device__ float g_xk[(size_t)SQ * KVD];
__device__ float g_xv[(size_t)SQ * KVD];
__device__ float g_att[(size_t)SQ * DIM];

__device__ __align__(16) __nv_bfloat16 g_xhi[(size_t)SQ * DIM];
__device__ __align__(16) __nv_bfloat16 g_xlo[(size_t)SQ * DIM];
__device__ __align__(16) __nv_bfloat16 g_atthi[(size_t)SQ * DIM];
__device__ __align__(16) __nv_bfloat16 g_attlo[(size_t)SQ * DIM];
__device__ __align__(16) __nv_bfloat16 g_qhi[(size_t)SQ * DIM];
__device__ __align__(16) __nv_bfloat16 g_qlo[(size_t)SQ * DIM];
__device__ __align__(16) __nv_bfloat16 g_khi[(size_t)SQ * KVD];
__device__ __align__(16) __nv_bfloat16 g_klo[(size_t)SQ * KVD];
__device__ __align__(16) __nv_bfloat16 g_vhi[(size_t)SQ * KVD];
__device__ __align__(16) __nv_bfloat16 g_vlo[(size_t)SQ * KVD];
__device__ __align__(16) __nv_bfloat16 g_wqT_hi[(size_t)DIM * DIM];
__device__ __align__(16) __nv_bfloat16 g_wqT_lo[(size_t)DIM * DIM];
__device__ __align__(16) __nv_bfloat16 g_wkT_hi[(size_t)KVD * DIM];
__device__ __align__(16) __nv_bfloat16 g_wkT_lo[(size_t)KVD * DIM];
__device__ __align__(16) __nv_bfloat16 g_wvT_hi[(size_t)KVD * DIM];
__device__ __align__(16) __nv_bfloat16 g_wvT_lo[(size_t)KVD * DIM];
__device__ __align__(16) __nv_bfloat16 g_woT_hi[(size_t)DIM * DIM];
__device__ __align__(16) __nv_bfloat16 g_woT_lo[(size_t)DIM * DIM];

__device__ __forceinline__ uint32_t smem_u32(const void* p) {
    return (uint32_t)__cvta_generic_to_shared(p);
}
#define LDSM_X4(r0, r1, r2, r3, addr)                                          \
    asm volatile("ldmatrix.sync.aligned.m8n8.x4.shared.b16 {%0,%1,%2,%3}, [%4];" \
                 : "=r"(r0), "=r"(r1), "=r"(r2), "=r"(r3) : "r"(addr))
#define LDSM_X2(r0, r1, addr)                                                  \
    asm volatile("ldmatrix.sync.aligned.m8n8.x2.shared.b16 {%0,%1}, [%2];"     \
                 : "=r"(r0), "=r"(r1) : "r"(addr))
#define LDSM_X4_T(r0, r1, r2, r3, addr)                                        \
    asm volatile("ldmatrix.sync.aligned.m8n8.x4.trans.shared.b16 {%0,%1,%2,%3}, [%4];" \
                 : "=r"(r0), "=r"(r1), "=r"(r2), "=r"(r3) : "r"(addr))
#define MMA16816(c, a, b0_, b1_)                                               \
    asm volatile("mma.sync.aligned.m16n8k16.row.col.f32.bf16.bf16.f32 "        \
                 "{%0,%1,%2,%3}, {%4,%5,%6,%7}, {%8,%9}, {%0,%1,%2,%3};"       \
                 : "+f"((c)[0]), "+f"((c)[1]), "+f"((c)[2]), "+f"((c)[3])      \
                 : "r"((a)[0]), "r"((a)[1]), "r"((a)[2]), "r"((a)[3]),         \
                   "r"(b0_), "r"(b1_))
__device__ __forceinline__ void cp16(uint32_t saddr, const void* g) {
    asm volatile("cp.async.cg.shared.global [%0], [%1], 16;"
                 :: "r"(saddr), "l"(g) : "memory");
}
#define CP_COMMIT() asm volatile("cp.async.commit_group;" ::: "memory")
#define CP_WAIT(n)  asm volatile("cp.async.wait_group %0;" :: "n"(n) : "memory")

__device__ __forceinline__ uint32_t pack_bf16x2(float lo, float hi) {
    uint32_t r;
    asm("cvt.rn.bf16x2.f32 %0, %1, %2;" : "=r"(r) : "f"(hi), "f"(lo));
    return r;
}
__device__ __forceinline__ float exp_fast(float x) {
    float t = fmaxf(x * 1.4426950408889634f, -126.0f);
    float fi = floorf(t);
    float f = t - fi;
    float p = fmaf(f, 0.0013333558f, 0.0096181291f);
    p = fmaf(f, p, 0.0555041087f);
    p = fmaf(f, p, 0.2402265069f);
    p = fmaf(f, p, 0.6931471806f);
    p = fmaf(f, p, 1.0f);
    int i = (int)fi;
    return __int_as_float((uint32_t)(i + 127) << 23) * p;
}

// ---------------- conversion kernels ----------------
__global__ __launch_bounds__(256)
void split_rows(const float* __restrict__ X, __nv_bfloat16* __restrict__ hi,
                __nv_bfloat16* __restrict__ lo)
{
    size_t i = (size_t)blockIdx.x * 256 + threadIdx.x;
    float v = X[i];
    __nv_bfloat16 h = __float2bfloat16(v);
    hi[i] = h;
    lo[i] = __float2bfloat16(v - __bfloat162float(h));
}

__global__ __launch_bounds__(256)
void transpose_split(const float* __restrict__ W, __nv_bfloat16* __restrict__ Thi,
                     __nv_bfloat16* __restrict__ Tlo, int K, int N)
{
    __shared__ float tile[32][33];
    int n0 = blockIdx.x * 32, k0 = blockIdx.y * 32;
    int tx = threadIdx.x & 31, ty = threadIdx.x >> 5;
#pragma unroll
    for (int j = 0; j < 4; j++)
        tile[ty + j * 8][tx] = W[(size_t)(k0 + ty + j * 8) * N + n0 + tx];
    __syncthreads();
#pragma unroll
    for (int j = 0; j < 4; j++) {
        float v = tile[tx][ty + j * 8];
        __nv_bfloat16 h = __float2bfloat16(v);
        __nv_bfloat16 l = __float2bfloat16(v - __bfloat162float(h));
        size_t o = (size_t)(n0 + ty + j * 8) * K + k0 + tx;
        Thi[o] = h;
        Tlo[o] = l;
    }
}

__global__ __launch_bounds__(256)
void rope_split(const float* __restrict__ t, const float* __restrict__ fc,
                const float* __restrict__ fs, __nv_bfloat16* __restrict__ hi,
                __nv_bfloat16* __restrict__ lo, int nh)
{
    int idx = blockIdx.x * blockDim.x + threadIdx.x;
    int p = idx & 63;
    int rest = idx >> 6;
    int h = rest % nh;
    int s = rest / nh;
    float c  = fc[s * 64 + p];
    float si = fs[s * 64 + p];
    const float* base = t + ((size_t)s * nh + h) * HD;
    float te = base[2 * p];
    float to = base[2 * p + 1];
    float e = te * c - to * si;
    float o = to * c + te * si;
    size_t off = ((size_t)s * nh + h) * HD + 2 * p;
    __nv_bfloat16 eh = __float2bfloat16(e);
    __nv_bfloat16 oh = __float2bfloat16(o);
    hi[off] = eh;
    hi[off + 1] = oh;
    lo[off] = __float2bfloat16(e - __bfloat162float(eh));
    lo[off + 1] = __float2bfloat16(o - __bfloat162float(oh));
}

// ---------------- fused split-3 HMMA GEMM, cp.async 2-stage ----------------
// Per K-chunk (32), stage Ahi/Alo/Bhi/Blo and do all 3 products.
#define SPITCH 40
#define TILE_E (128 * SPITCH)           // elems per tile
#define SLOT_E (4 * TILE_E)             // Ah Al Bh Bl
#define GEMM_SMEM (2 * SLOT_E * 2)      // bytes, 2 slots = 81920

__global__ void __launch_bounds__(256, 2)
gemm_fused(const __nv_bfloat16* __restrict__ Ahi, const __nv_bfloat16* __restrict__ Alo,
           const __nv_bfloat16* __restrict__ Bhi, const __nv_bfloat16* __restrict__ Blo,
           float* __restrict__ C, int ldc)
{
    extern __shared__ __nv_bfloat16 dsm[];
    int tid = threadIdx.x, wid = tid >> 5, lane = tid & 31;
    int m0 = blockIdx.y * 128, n0 = blockIdx.x * 128;
    int wm = (wid & 1) * 64, wn = (wid >> 1) * 32;

    int srow = tid >> 1;
    int shalf = (tid & 1) * 16;   // elem offset within 32-wide chunk

    uint32_t smbase = smem_u32(dsm);

    float acc[4][4][4];
#pragma unroll
    for (int i = 0; i < 4; i++)
#pragma unroll
        for (int j = 0; j < 4; j++)
#pragma unroll
            for (int c = 0; c < 4; c++) acc[i][j][c] = 0.f;

    // ---- staging lambda (manual) ----
    // chunk c -> slot s
    auto stage = [&](int c, int s) {
        size_t gA = (size_t)(m0 + srow) * KTOT + c * 32 + shalf;
        size_t gB = (size_t)(n0 + srow) * KTOT + c * 32 + shalf;
        uint32_t sb = smbase + (uint32_t)s * (SLOT_E * 2);
        uint32_t so = (uint32_t)(srow * SPITCH + shalf) * 2;
        cp16(sb + so,                  Ahi + gA);
        cp16(sb + so + 16,             Ahi + gA + 8);
        cp16(sb + TILE_E * 2 + so,     Alo + gA);
        cp16(sb + TILE_E * 2 + so + 16, Alo + gA + 8);
        cp16(sb + TILE_E * 4 + so,     Bhi + gB);
        cp16(sb + TILE_E * 4 + so + 16, Bhi + gB + 8);
        cp16(sb + TILE_E * 6 + so,     Blo + gB);
        cp16(sb + TILE_E * 6 + so + 16, Blo + gB + 8);
    };

    stage(0, 0);
    CP_COMMIT();

    const int NCH = KTOT / 32;   // 128
    for (int t = 0; t < NCH; t++) {
        if (t + 1 < NCH) { stage(t + 1, (t + 1) & 1); CP_COMMIT(); CP_WAIT(1); }
        else             { CP_WAIT(0); }
        __syncthreads();

        uint32_t sb = smbase + (uint32_t)(t & 1) * (SLOT_E * 2);
        uint32_t aH = sb, aL = sb + TILE_E * 2, bH = sb + TILE_E * 4, bL = sb + TILE_E * 6;

#pragma unroll
        for (int ks = 0; ks < 2; ks++) {
            uint32_t bh[4][2], bl[4][2];
#pragma unroll
            for (int jn = 0; jn < 4; jn++) {
                uint32_t off = (uint32_t)((wn + jn * 8 + (lane & 7)) * SPITCH +
                                          ks * 16 + ((lane >> 3) & 1) * 8) * 2;
                LDSM_X2(bh[jn][0], bh[jn][1], bH + off);
                LDSM_X2(bl[jn][0], bl[jn][1], bL + off);
            }
#pragma unroll
            for (int mi = 0; mi < 4; mi++) {
                uint32_t off = (uint32_t)((wm + mi * 16 + (lane & 15)) * SPITCH +
                                          ks * 16 + ((lane >> 4) << 3)) * 2;
                uint32_t ah[4], al[4];
                LDSM_X4(ah[0], ah[1], ah[2], ah[3], aH + off);
                LDSM_X4(al[0], al[1], al[2], al[3], aL + off);
#pragma unroll
                for (int jn = 0; jn < 4; jn++) {
                    MMA16816(acc[mi][jn], ah, bh[jn][0], bh[jn][1]);
                    MMA16816(acc[mi][jn], ah, bl[jn][0], bl[jn][1]);
                    MMA16816(acc[mi][jn], al, bh[jn][0], bh[jn][1]);
                }
            }
        }
        __syncthreads();
    }

    int qr = lane >> 2;
    int qc = (lane & 3) * 2;
#pragma unroll
    for (int mi = 0; mi < 4; mi++) {
#pragma unroll
        for (int jn = 0; jn < 4; jn++) {
            int row = m0 + wm + mi * 16 + qr;
            int col = n0 + wn + jn * 8 + qc;
            *(float2*)&C[(size_t)row * ldc + col] =
                make_float2(acc[mi][jn][0], acc[mi][jn][1]);
            *(float2*)&C[(size_t)(row + 8) * ldc + col] =
                make_float2(acc[mi][jn][2], acc[mi][jn][3]);
        }
    }
}

// ---------------- HMMA flash attention (split-3, cp.async K/V groups) ----------------
#define PIT 136
#define FLASH_SMEM (6 * 128 * PIT * 2)   // 208896 B

__global__ __launch_bounds__(256, 1)
void flash_mma(const __nv_bfloat16* __restrict__ Qhi, const __nv_bfloat16* __restrict__ Qlo,
               const __nv_bfloat16* __restrict__ Khi, const __nv_bfloat16* __restrict__ Klo,
               const __nv_bfloat16* __restrict__ Vhi, const __nv_bfloat16* __restrict__ Vlo,
               float* __restrict__ Ob)
{
    extern __shared__ __nv_bfloat16 smf[];
    __nv_bfloat16* sQh = smf;
    __nv_bfloat16* sQl = smf + 128 * PIT;
    __nv_bfloat16* sKh = smf + 2 * 128 * PIT;
    __nv_bfloat16* sKl = smf + 3 * 128 * PIT;
    __nv_bfloat16* sVh = smf + 4 * 128 * PIT;
    __nv_bfloat16* sVl = smf + 5 * 128 * PIT;

    int h  = blockIdx.y;
    int qt = (gridDim.x - 1) - blockIdx.x;
    int m0 = qt * 128;
    int kvh = h & 7;

    int tid = threadIdx.x, w = tid >> 5, lane = tid & 31;
    int gr = lane >> 2;
    int qc = (lane & 3) * 2;

    // stage Q (once)
#pragma unroll
    for (int it = 0; it < 8; it++) {
        int idx = it * 256 + tid;
        int row = idx >> 4, c4 = idx & 15;
        *(uint4*)&sQh[row * PIT + c4 * 8] =
            *(const uint4*)(Qhi + (size_t)(m0 + row) * DIM + h * HD + c4 * 8);
        *(uint4*)&sQl[row * PIT + c4 * 8] =
            *(const uint4*)(Qlo + (size_t)(m0 + row) * DIM + h * HD + c4 * 8);
    }
    __syncthreads();

    float o[16][4];
#pragma unroll
    for (int j = 0; j < 16; j++)
#pragma unroll
        for (int c = 0; c < 4; c++) o[j][c] = 0.f;
    float mrow[2] = {-INFINITY, -INFINITY};
    float lrow[2] = {0.f, 0.f};
    const float scale = 0.08838834764831845f;

    for (int kt = 0; kt <= qt; kt++) {
        int n0 = kt * 128;

        // ---- issue K group then V group ----
#pragma unroll
        for (int it = 0; it < 8; it++) {
            int idx = it * 256 + tid;
            int row = idx >> 4, c4 = idx & 15;
            size_t g = (size_t)(n0 + row) * KVD + kvh * HD + c4 * 8;
            uint32_t so = (uint32_t)(row * PIT + c4 * 8) * 2;
            cp16(smem_u32(sKh) + so, Khi + g);
            cp16(smem_u32(sKl) + so, Klo + g);
        }
        CP_COMMIT();
#pragma unroll
        for (int it = 0; it < 8; it++) {
            int idx = it * 256 + tid;
            int row = idx >> 4, c4 = idx & 15;
            size_t g = (size_t)(n0 + row) * KVD + kvh * HD + c4 * 8;
            uint32_t so = (uint32_t)(row * PIT + c4 * 8) * 2;
            cp16(smem_u32(sVh) + so, Vhi + g);
            cp16(smem_u32(sVl) + so, Vlo + g);
        }
        CP_COMMIT();

        CP_WAIT(1);            // K ready; V may still be in flight
        __syncthreads();

        // ---- S = Q K^T, fused 3 products with shared K frags ----
        float s[16][4];
#pragma unroll
        for (int j = 0; j < 16; j++)
#pragma unroll
            for (int c = 0; c < 4; c++) s[j][c] = 0.f;

#pragma unroll
        for (int g = 0; g < 4; g++) {
            uint32_t a0h[4], a1h[4], a0l[4], a1l[4];
            uint32_t offA = (uint32_t)((w * 16 + (lane & 15)) * PIT + g * 32 +
                                       ((lane >> 4) << 3)) * 2;
            LDSM_X4(a0h[0], a0h[1], a0h[2], a0h[3], smem_u32(sQh) + offA);
            LDSM_X4(a1h[0], a1h[1], a1h[2], a1h[3], smem_u32(sQh) + offA + 32);
            LDSM_X4(a0l[0], a0l[1], a0l[2], a0l[3], smem_u32(sQl) + offA);
            LDSM_X4(a1l[0], a1l[1], a1l[2], a1l[3], smem_u32(sQl) + offA + 32);
#pragma unroll
            for (int jn = 0; jn < 16; jn++) {
                uint32_t offB = (uint32_t)((jn * 8 + (lane & 7)) * PIT + g * 32 +
                                           ((lane >> 3) << 3)) * 2;
                uint32_t bh0, bh1, bh2, bh3, bl0, bl1, bl2, bl3;
                LDSM_X4(bh0, bh1, bh2, bh3, smem_u32(sKh) + offB);
                LDSM_X4(bl0, bl1, bl2, bl3, smem_u32(sKl) + offB);
                MMA16816(s[jn], a0h, bh0, bh1);
                MMA16816(s[jn], a1h, bh2, bh3);
                MMA16816(s[jn], a0h, bl0, bl1);
                MMA16816(s[jn], a1h, bl2, bl3);
                MMA16816(s[jn], a0l, bh0, bh1);
                MMA16816(s[jn], a1l, bh2, bh3);
            }
        }

        // ---- scale + causal mask ----
        if (kt == qt) {
#pragma unroll
            for (int jn = 0; jn < 16; jn++) {
                int c0 = jn * 8 + qc;
                int r0 = w * 16 + gr;
                s[jn][0] = (c0     > r0    ) ? -1e30f : s[jn][0] * scale;
                s[jn][1] = (c0 + 1 > r0    ) ? -1e30f : s[jn][1] * scale;
                s[jn][2] = (c0     > r0 + 8) ? -1e30f : s[jn][2] * scale;
                s[jn][3] = (c0 + 1 > r0 + 8) ? -1e30f : s[jn][3] * scale;
            }
        } else {
#pragma unroll
            for (int jn = 0; jn < 16; jn++)
#pragma unroll
                for (int c = 0; c < 4; c++) s[jn][c] *= scale;
        }

        // ---- online softmax ----
#pragma unroll
        for (int half = 0; half < 2; half++) {
            int b = half * 2;
            float tmax = s[0][b];
#pragma unroll
            for (int jn = 0; jn < 16; jn++)
                tmax = fmaxf(tmax, fmaxf(s[jn][b], s[jn][b + 1]));
            tmax = fmaxf(tmax, __shfl_xor_sync(0xffffffffu, tmax, 1));
            tmax = fmaxf(tmax, __shfl_xor_sync(0xffffffffu, tmax, 2));

            float mnew = fmaxf(mrow[half], tmax);
            float alpha = exp_fast(mrow[half] - mnew);
            mrow[half] = mnew;

            float rsum = 0.f;
#pragma unroll
            for (int jn = 0; jn < 16; jn++) {
                float p0 = exp_fast(s[jn][b] - mnew);
                float p1 = exp_fast(s[jn][b + 1] - mnew);
                s[jn][b] = p0;
                s[jn][b + 1] = p1;
                rsum += p0 + p1;
            }
            rsum += __shfl_xor_sync(0xffffffffu, rsum, 1);
            rsum += __shfl_xor_sync(0xffffffffu, rsum, 2);

            lrow[half] = lrow[half] * alpha + rsum;
#pragma unroll
            for (int jn = 0; jn < 16; jn++) {
                o[jn][b]     *= alpha;
                o[jn][b + 1] *= alpha;
            }
        }

        // ---- P -> bf16 hi/lo fragments (register-only) ----
        uint32_t ph[8][4], pl[8][4];
#pragma unroll
        for (int ks = 0; ks < 8; ks++) {
#pragma unroll
            for (int q = 0; q < 4; q++) {
                int jn = 2 * ks + (q >> 1);
                int c  = (q & 1) * 2;
                float f0 = s[jn][c], f1 = s[jn][c + 1];
                uint32_t hp = pack_bf16x2(f0, f1);
                ph[ks][q] = hp;
                float h0 = __uint_as_float(hp << 16);
                float h1 = __uint_as_float(hp & 0xffff0000u);
                pl[ks][q] = pack_bf16x2(f0 - h0, f1 - h1);
            }
        }

        CP_WAIT(0);            // V ready
        __syncthreads();

        // ---- O += P V, fused 3 products with shared V frags ----
#pragma unroll
        for (int ks = 0; ks < 8; ks++) {
#pragma unroll
            for (int jp = 0; jp < 8; jp++) {
                uint32_t offV = (uint32_t)((ks * 16 + (lane & 7) + ((lane >> 3) & 1) * 8) * PIT +
                                           jp * 16 + ((lane >> 4) << 3)) * 2;
                uint32_t vh0, vh1, vh2, vh3, vl0, vl1, vl2, vl3;
                LDSM_X4_T(vh0, vh1, vh2, vh3, smem_u32(sVh) + offV);
                LDSM_X4_T(vl0, vl1, vl2, vl3, smem_u32(sVl) + offV);
                MMA16816(o[2 * jp],     ph[ks], vh0, vh1);
                MMA16816(o[2 * jp + 1], ph[ks], vh2, vh3);
                MMA16816(o[2 * jp],     ph[ks], vl0, vl1);
                MMA16816(o[2 * jp + 1], ph[ks], vl2, vl3);
                MMA16816(o[2 * jp],     pl[ks], vh0, vh1);
                MMA16816(o[2 * jp + 1], pl[ks], vh2, vh3);
            }
        }
        __syncthreads();  // protect K/V buffers before next iteration's cp.async
    }

    // ---- epilogue ----
    float inv0 = 1.f / lrow[0], inv1 = 1.f / lrow[1];
    int row0 = m0 + w * 16 + gr;
#pragma unroll
    for (int jn = 0; jn < 16; jn++) {
        int col = h * HD + jn * 8 + qc;
        *(float2*)&Ob[(size_t)row0 * DIM + col] =
            make_float2(o[jn][0] * inv0, o[jn][1] * inv0);
        *(float2*)&Ob[(size_t)(row0 + 8) * DIM + col] =
            make_float2(o[jn][2] * inv1, o[jn][3] * inv1);
    }
}

// ---------------- launch ----------------
extern "C" void kernel_launch(void* const* d_in, const int* in_sizes, int n_in,
                              void* d_out, int out_size)
{
    const float* x  = (const float*)d_in[0];
    const float* wq = (const float*)d_in[1];
    const float* wk = (const float*)d_in[2];
    const float* wv = (const float*)d_in[3];
    const float* wo = (const float*)d_in[4];
    const float* fc = (const float*)d_in[5];
    const float* fs = (const float*)d_in[6];
    float* out = (float*)d_out;

    float *pxq, *pxk, *pxv, *patt;
    __nv_bfloat16 *pxhi, *pxlo, *pahi, *palo;
    __nv_bfloat16 *pqh, *pql, *pkh, *pkl, *pvh, *pvl;
    __nv_bfloat16 *pwqh, *pwql, *pwkh, *pwkl, *pwvh, *pwvl, *pwoh, *pwol;
    cudaGetSymbolAddress((void**)&pxq,  g_xq);
    cudaGetSymbolAddress((void**)&pxk,  g_xk);
    cudaGetSymbolAddress((void**)&pxv,  g_xv);
    cudaGetSymbolAddress((void**)&patt, g_att);
    cudaGetSymbolAddress((void**)&pxhi, g_xhi);
    cudaGetSymbolAddress((void**)&pxlo, g_xlo);
    cudaGetSymbolAddress((void**)&pahi, g_atthi);
    cudaGetSymbolAddress((void**)&palo, g_attlo);
    cudaGetSymbolAddress((void**)&pqh,  g_qhi);
    cudaGetSymbolAddress((void**)&pql,  g_qlo);
    cudaGetSymbolAddress((void**)&pkh,  g_khi);
    cudaGetSymbolAddress((void**)&pkl,  g_klo);
    cudaGetSymbolAddress((void**)&pvh,  g_vhi);
    cudaGetSymbolAddress((void**)&pvl,  g_vlo);
    cudaGetSymbolAddress((void**)&pwqh, g_wqT_hi);
    cudaGetSymbolAddress((void**)&pwql, g_wqT_lo);
    cudaGetSymbolAddress((void**)&pwkh, g_wkT_hi);
    cudaGetSymbolAddress((void**)&pwkl, g_wkT_lo);
    cudaGetSymbolAddress((void**)&pwvh, g_wvT_hi);
    cudaGetSymbolAddress((void**)&pwvl, g_wvT_lo);
    cudaGetSymbolAddress((void**)&pwoh, g_woT_hi);
    cudaGetSymbolAddress((void**)&pwol, g_woT_lo);

    static bool attr_set = false;
    if (!attr_set) {
        cudaFuncSetAttribute(flash_mma, cudaFuncAttributeMaxDynamicSharedMemorySize,
                             FLASH_SMEM);
        cudaFuncSetAttribute(gemm_fused, cudaFuncAttributeMaxDynamicSharedMemorySize,
                             GEMM_SMEM);
        attr_set = true;
    }

    // ---- conversions ----
    split_rows<<<(SQ * DIM) / 256, 256>>>(x, pxhi, pxlo);
    transpose_split<<<dim3(DIM / 32, DIM / 32), 256>>>(wq, pwqh, pwql, DIM, DIM);
    transpose_split<<<dim3(KVD / 32, DIM / 32), 256>>>(wk, pwkh, pwkl, DIM, KVD);
    transpose_split<<<dim3(KVD / 32, DIM / 32), 256>>>(wv, pwvh, pwvl, DIM, KVD);
    transpose_split<<<dim3(DIM / 32, DIM / 32), 256>>>(wo, pwoh, pwol, DIM, DIM);

    // ---- QKV projections ----
    gemm_fused<<<dim3(DIM / 128, SQ / 128), 256, GEMM_SMEM>>>(pxhi, pxlo, pwqh, pwql, pxq, DIM);
    gemm_fused<<<dim3(KVD / 128, SQ / 128), 256, GEMM_SMEM>>>(pxhi, pxlo, pwkh, pwkl, pxk, KVD);
    gemm_fused<<<dim3(KVD / 128, SQ / 128), 256, GEMM_SMEM>>>(pxhi, pxlo, pwvh, pwvl, pxv, KVD);

    // ---- RoPE -> bf16 hi/lo; V split ----
    rope_split<<<(SQ * NH * 64) / 256, 256>>>(pxq, fc, fs, pqh, pql, NH);
    rope_split<<<(SQ * NKVH * 64) / 256, 256>>>(pxk, fc, fs, pkh, pkl, NKVH);
    split_rows<<<(SQ * KVD) / 256, 256>>>(pxv, pvh, pvl);

    // ---- fused attention ----
    flash_mma<<<dim3(SQ / 128, NH), 256, FLASH_SMEM>>>(pqh, pql, pkh, pkl, pvh, pvl, patt);

    // ---- output projection ----
    split_rows<<<(SQ * DIM) / 256, 256>>>(patt, pahi, palo);
    gemm_fused<<<dim3(DIM / 128, SQ / 128), 256, GEMM_SMEM>>>(pahi, palo, pwoh, pwol, out, DIM);
}

// round 11
// speedup vs baseline: 2.8358x; 1.0439x over previous
#include <cuda_runtime.h>
#include <cuda_bf16.h>
#include <math.h>
#include <stdint.h>

#define SQ   2048
#define DIM  4096
#define NH   32
#define NKVH 8
#define HD   128
#define KVD  (NKVH*HD)   // 1024
#define KTOT 4096

// ---------------- scratch ----------------
__device__ __align__(16) __nv_bfloat16 g_xhi[(size_t)SQ * DIM];
__device__ __align__(16) __nv_bfloat16 g_xlo[(size_t)SQ * DIM];
__device__ __align__(16) __nv_bfloat16 g_atthi[(size_t)SQ * DIM];
__device__ __align__(16) __nv_bfloat16 g_attlo[(size_t)SQ * DIM];
__device__ __align__(16) __nv_bfloat16 g_qhi[(size_t)SQ * DIM];
__device__ __align__(16) __nv_bfloat16 g_qlo[(size_t)SQ * DIM];
__device__ __align__(16) __nv_bfloat16 g_khi[(size_t)SQ * KVD];
__device__ __align__(16) __nv_bfloat16 g_klo[(size_t)SQ * KVD];
__device__ __align__(16) __nv_bfloat16 g_vhi[(size_t)SQ * KVD];
__device__ __align__(16) __nv_bfloat16 g_vlo[(size_t)SQ * KVD];
__device__ __align__(16) __nv_bfloat16 g_wqT_hi[(size_t)DIM * DIM];
__device__ __align__(16) __nv_bfloat16 g_wqT_lo[(size_t)DIM * DIM];
__device__ __align__(16) __nv_bfloat16 g_wkT_hi[(size_t)KVD * DIM];
__device__ __align__(16) __nv_bfloat16 g_wkT_lo[(size_t)KVD * DIM];
__device__ __align__(16) __nv_bfloat16 g_wvT_hi[(size_t)KVD * DIM];
__device__ __align__(16) __nv_bfloat16 g_wvT_lo[(size_t)KVD * DIM];
__device__ __align__(16) __nv_bfloat16 g_woT_hi[(size_t)DIM * DIM];
__device__ __align__(16) __nv_bfloat16 g_woT_lo[(size_t)DIM * DIM];

__device__ __forceinline__ uint32_t smem_u32(const void* p) {
    return (uint32_t)__cvta_generic_to_shared(p);
}
#define LDSM_X4(r0, r1, r2, r3, addr)                                          \
    asm volatile("ldmatrix.sync.aligned.m8n8.x4.shared.b16 {%0,%1,%2,%3}, [%4];" \
                 : "=r"(r0), "=r"(r1), "=r"(r2), "=r"(r3) : "r"(addr))
#define LDSM_X2(r0, r1, addr)                                                  \
    asm volatile("ldmatrix.sync.aligned.m8n8.x2.shared.b16 {%0,%1}, [%2];"     \
                 : "=r"(r0), "=r"(r1) : "r"(addr))
#define LDSM_X4_T(r0, r1, r2, r3, addr)                                        \
    asm volatile("ldmatrix.sync.aligned.m8n8.x4.trans.shared.b16 {%0,%1,%2,%3}, [%4];" \
                 : "=r"(r0), "=r"(r1), "=r"(r2), "=r"(r3) : "r"(addr))
#define MMA16816(c, a, b0_, b1_)                                               \
    asm volatile("mma.sync.aligned.m16n8k16.row.col.f32.bf16.bf16.f32 "        \
                 "{%0,%1,%2,%3}, {%4,%5,%6,%7}, {%8,%9}, {%0,%1,%2,%3};"       \
                 : "+f"((c)[0]), "+f"((c)[1]), "+f"((c)[2]), "+f"((c)[3])      \
                 : "r"((a)[0]), "r"((a)[1]), "r"((a)[2]), "r"((a)[3]),         \
                   "r"(b0_), "r"(b1_))
__device__ __forceinline__ void cp16(uint32_t saddr, const void* g) {
    asm volatile("cp.async.cg.shared.global [%0], [%1], 16;"
                 :: "r"(saddr), "l"(g) : "memory");
}
#define CP_COMMIT() asm volatile("cp.async.commit_group;" ::: "memory")
#define CP_WAIT(n)  asm volatile("cp.async.wait_group %0;" :: "n"(n) : "memory")

__device__ __forceinline__ uint32_t pack_bf16x2(float lo, float hi) {
    uint32_t r;
    asm("cvt.rn.bf16x2.f32 %0, %1, %2;" : "=r"(r) : "f"(hi), "f"(lo));
    return r;
}
__device__ __forceinline__ float exp_fast(float x) {
    float t = fmaxf(x * 1.4426950408889634f, -126.0f);
    float fi = floorf(t);
    float f = t - fi;
    float p = fmaf(f, 0.0013333558f, 0.0096181291f);
    p = fmaf(f, p, 0.0555041087f);
    p = fmaf(f, p, 0.2402265069f);
    p = fmaf(f, p, 0.6931471806f);
    p = fmaf(f, p, 1.0f);
    int i = (int)fi;
    return __int_as_float((uint32_t)(i + 127) << 23) * p;
}

// ---------------- conversion kernels ----------------
__global__ __launch_bounds__(256)
void split_rows(const float* __restrict__ X, __nv_bfloat16* __restrict__ hi,
                __nv_bfloat16* __restrict__ lo)
{
    size_t i = (size_t)blockIdx.x * 256 + threadIdx.x;
    float v = X[i];
    __nv_bfloat16 h = __float2bfloat16(v);
    hi[i] = h;
    lo[i] = __float2bfloat16(v - __bfloat162float(h));
}

__global__ __launch_bounds__(256)
void transpose_split(const float* __restrict__ W, __nv_bfloat16* __restrict__ Thi,
                     __nv_bfloat16* __restrict__ Tlo, int K, int N)
{
    __shared__ float tile[32][33];
    int n0 = blockIdx.x * 32, k0 = blockIdx.y * 32;
    int tx = threadIdx.x & 31, ty = threadIdx.x >> 5;
#pragma unroll
    for (int j = 0; j < 4; j++)
        tile[ty + j * 8][tx] = W[(size_t)(k0 + ty + j * 8) * N + n0 + tx];
    __syncthreads();
#pragma unroll
    for (int j = 0; j < 4; j++) {
        float v = tile[tx][ty + j * 8];
        __nv_bfloat16 h = __float2bfloat16(v);
        __nv_bfloat16 l = __float2bfloat16(v - __bfloat162float(h));
        size_t o = (size_t)(n0 + ty + j * 8) * K + k0 + tx;
        Thi[o] = h;
        Tlo[o] = l;
    }
}

// ---------------- QKV mega-GEMM: CTA 128x256, warps 64x64, 3-stage cp.async ----
// x tiles: 0-15 Q (cols 0-4095), 16-19 K (0-1023), 20-23 V (0-1023).
// Epilogue: Q/K rope + bf16 hi/lo split; V bf16 split.
#define SPITCH 40
#define AOFF_L (128 * SPITCH)                 // elems
#define BOFF_H (2 * 128 * SPITCH)
#define BOFF_L (2 * 128 * SPITCH + 256 * SPITCH)
#define SLOT_EL (SPITCH * (128 + 128 + 256 + 256))   // 30720 elems
#define QKV_SMEM (3 * SLOT_EL * 2)                   // 184320 bytes

struct QkvOut {
    const __nv_bfloat16 *bh, *bl;
    __nv_bfloat16 *oh, *ol;
    int nloc, ldo, rope;
};

__global__ void __launch_bounds__(256, 1)
gemm_qkv(const __nv_bfloat16* __restrict__ Ahi, const __nv_bfloat16* __restrict__ Alo,
         const __nv_bfloat16* __restrict__ Wqh, const __nv_bfloat16* __restrict__ Wql,
         const __nv_bfloat16* __restrict__ Wkh, const __nv_bfloat16* __restrict__ Wkl,
         const __nv_bfloat16* __restrict__ Wvh, const __nv_bfloat16* __restrict__ Wvl,
         __nv_bfloat16* __restrict__ Qh, __nv_bfloat16* __restrict__ Ql,
         __nv_bfloat16* __restrict__ Kh, __nv_bfloat16* __restrict__ Kl,
         __nv_bfloat16* __restrict__ Vh, __nv_bfloat16* __restrict__ Vl,
         const float* __restrict__ fc, const float* __restrict__ fs)
{
    extern __shared__ __nv_bfloat16 dsm[];
    int tid = threadIdx.x, wid = tid >> 5, lane = tid & 31;
    int m0 = blockIdx.y * 128;
    int xb = blockIdx.x;

    QkvOut oc;
    if (xb < 16)      { oc = {Wqh, Wql, Qh, Ql, xb * 256, DIM, 1}; }
    else if (xb < 20) { oc = {Wkh, Wkl, Kh, Kl, (xb - 16) * 256, KVD, 1}; }
    else              { oc = {Wvh, Wvl, Vh, Vl, (xb - 20) * 256, KVD, 0}; }

    int wm = (wid & 1) * 64, wn = (wid >> 1) * 64;
    uint32_t smbase = smem_u32(dsm);

    int arow = tid >> 1, ahalf = (tid & 1) * 16;

    float acc[4][8][4];
#pragma unroll
    for (int i = 0; i < 4; i++)
#pragma unroll
        for (int j = 0; j < 8; j++)
#pragma unroll
            for (int c = 0; c < 4; c++) acc[i][j][c] = 0.f;

    auto stage = [&](int c, int s) {
        uint32_t sb = smbase + (uint32_t)s * (SLOT_EL * 2);
        size_t gA = (size_t)(m0 + arow) * KTOT + c * 32 + ahalf;
        uint32_t ao = (uint32_t)(arow * SPITCH + ahalf) * 2;
        cp16(sb + ao,                    Ahi + gA);
        cp16(sb + ao + 16,               Ahi + gA + 8);
        cp16(sb + AOFF_L * 2 + ao,       Alo + gA);
        cp16(sb + AOFF_L * 2 + ao + 16,  Alo + gA + 8);
#pragma unroll
        for (int j = 0; j < 2; j++) {
            int brow = arow + j * 128;
            size_t gB = (size_t)(oc.nloc + brow) * KTOT + c * 32 + ahalf;
            uint32_t bo = (uint32_t)(brow * SPITCH + ahalf) * 2;
            cp16(sb + BOFF_H * 2 + bo,      oc.bh + gB);
            cp16(sb + BOFF_H * 2 + bo + 16, oc.bh + gB + 8);
            cp16(sb + BOFF_L * 2 + bo,      oc.bl + gB);
            cp16(sb + BOFF_L * 2 + bo + 16, oc.bl + gB + 8);
        }
    };

    const int NCH = KTOT / 32;  // 128
    stage(0, 0); CP_COMMIT();
    stage(1, 1); CP_COMMIT();

    for (int t = 0; t < NCH; t++) {
        CP_WAIT(1);
        __syncthreads();
        int slot = t % 3;
        uint32_t sb = smbase + (uint32_t)slot * (SLOT_EL * 2);
        uint32_t aH = sb, aL = sb + AOFF_L * 2, bH = sb + BOFF_H * 2, bL = sb + BOFF_L * 2;

#pragma unroll
        for (int ks = 0; ks < 2; ks++) {
            uint32_t bh[8][2], bl[8][2];
#pragma unroll
            for (int jn = 0; jn < 8; jn++) {
                uint32_t off = (uint32_t)((wn + jn * 8 + (lane & 7)) * SPITCH +
                                          ks * 16 + ((lane >> 3) & 1) * 8) * 2;
                LDSM_X2(bh[jn][0], bh[jn][1], bH + off);
                LDSM_X2(bl[jn][0], bl[jn][1], bL + off);
            }
#pragma unroll
            for (int mi = 0; mi < 4; mi++) {
                uint32_t off = (uint32_t)((wm + mi * 16 + (lane & 15)) * SPITCH +
                                          ks * 16 + ((lane >> 4) << 3)) * 2;
                uint32_t ah[4], al[4];
                LDSM_X4(ah[0], ah[1], ah[2], ah[3], aH + off);
                LDSM_X4(al[0], al[1], al[2], al[3], aL + off);
#pragma unroll
                for (int jn = 0; jn < 8; jn++) {
                    MMA16816(acc[mi][jn], ah, bh[jn][0], bh[jn][1]);
                    MMA16816(acc[mi][jn], ah, bl[jn][0], bl[jn][1]);
                    MMA16816(acc[mi][jn], al, bh[jn][0], bh[jn][1]);
                }
            }
        }
        __syncthreads();
        if (t + 2 < NCH) { stage(t + 2, (t + 2) % 3); CP_COMMIT(); }
    }

    // ---- epilogue ----
    int qr = lane >> 2, qc = (lane & 3) * 2;
#pragma unroll
    for (int mi = 0; mi < 4; mi++) {
#pragma unroll
        for (int jn = 0; jn < 8; jn++) {
            int r0 = m0 + wm + mi * 16 + qr;
            int cl = oc.nloc + wn + jn * 8 + qc;
            float v00 = acc[mi][jn][0], v01 = acc[mi][jn][1];
            float v10 = acc[mi][jn][2], v11 = acc[mi][jn][3];
            if (oc.rope) {
                int p = (cl & 127) >> 1;
                float c0 = fc[r0 * 64 + p],       s0 = fs[r0 * 64 + p];
                float c1 = fc[(r0 + 8) * 64 + p], s1 = fs[(r0 + 8) * 64 + p];
                float e0 = v00 * c0 - v01 * s0, o0 = v01 * c0 + v00 * s0;
                float e1 = v10 * c1 - v11 * s1, o1 = v11 * c1 + v10 * s1;
                v00 = e0; v01 = o0; v10 = e1; v11 = o1;
            }
            uint32_t hw0 = pack_bf16x2(v00, v01);
            uint32_t lw0 = pack_bf16x2(v00 - __uint_as_float(hw0 << 16),
                                       v01 - __uint_as_float(hw0 & 0xffff0000u));
            uint32_t hw1 = pack_bf16x2(v10, v11);
            uint32_t lw1 = pack_bf16x2(v10 - __uint_as_float(hw1 << 16),
                                       v11 - __uint_as_float(hw1 & 0xffff0000u));
            *(uint32_t*)&oc.oh[(size_t)r0 * oc.ldo + cl]       = hw0;
            *(uint32_t*)&oc.ol[(size_t)r0 * oc.ldo + cl]       = lw0;
            *(uint32_t*)&oc.oh[(size_t)(r0 + 8) * oc.ldo + cl] = hw1;
            *(uint32_t*)&oc.ol[(size_t)(r0 + 8) * oc.ldo + cl] = lw1;
        }
    }
}

// ---------------- O projection: same mainloop, fp32 epilogue ----------------
__global__ void __launch_bounds__(256, 1)
gemm_out(const __nv_bfloat16* __restrict__ Ahi, const __nv_bfloat16* __restrict__ Alo,
         const __nv_bfloat16* __restrict__ Bhi, const __nv_bfloat16* __restrict__ Blo,
         float* __restrict__ C)
{
    extern __shared__ __nv_bfloat16 dsm[];
    int tid = threadIdx.x, wid = tid >> 5, lane = tid & 31;
    int m0 = blockIdx.y * 128, n0 = blockIdx.x * 256;
    int wm = (wid & 1) * 64, wn = (wid >> 1) * 64;
    uint32_t smbase = smem_u32(dsm);
    int arow = tid >> 1, ahalf = (tid & 1) * 16;

    float acc[4][8][4];
#pragma unroll
    for (int i = 0; i < 4; i++)
#pragma unroll
        for (int j = 0; j < 8; j++)
#pragma unroll
            for (int c = 0; c < 4; c++) acc[i][j][c] = 0.f;

    auto stage = [&](int c, int s) {
        uint32_t sb = smbase + (uint32_t)s * (SLOT_EL * 2);
        size_t gA = (size_t)(m0 + arow) * KTOT + c * 32 + ahalf;
        uint32_t ao = (uint32_t)(arow * SPITCH + ahalf) * 2;
        cp16(sb + ao,                   Ahi + gA);
        cp16(sb + ao + 16,              Ahi + gA + 8);
        cp16(sb + AOFF_L * 2 + ao,      Alo + gA);
        cp16(sb + AOFF_L * 2 + ao + 16, Alo + gA + 8);
#pragma unroll
        for (int j = 0; j < 2; j++) {
            int brow = arow + j * 128;
            size_t gB = (size_t)(n0 + brow) * KTOT + c * 32 + ahalf;
            uint32_t bo = (uint32_t)(brow * SPITCH + ahalf) * 2;
            cp16(sb + BOFF_H * 2 + bo,      Bhi + gB);
            cp16(sb + BOFF_H * 2 + bo + 16, Bhi + gB + 8);
            cp16(sb + BOFF_L * 2 + bo,      Blo + gB);
            cp16(sb + BOFF_L * 2 + bo + 16, Blo + gB + 8);
        }
    };

    const int NCH = KTOT / 32;
    stage(0, 0); CP_COMMIT();
    stage(1, 1); CP_COMMIT();

    for (int t = 0; t < NCH; t++) {
        CP_WAIT(1);
        __syncthreads();
        int slot = t % 3;
        uint32_t sb = smbase + (uint32_t)slot * (SLOT_EL * 2);
        uint32_t aH = sb, aL = sb + AOFF_L * 2, bH = sb + BOFF_H * 2, bL = sb + BOFF_L * 2;

#pragma unroll
        for (int ks = 0; ks < 2; ks++) {
            uint32_t bh[8][2], bl[8][2];
#pragma unroll
            for (int jn = 0; jn < 8; jn++) {
                uint32_t off = (uint32_t)((wn + jn * 8 + (lane & 7)) * SPITCH +
                                          ks * 16 + ((lane >> 3) & 1) * 8) * 2;
                LDSM_X2(bh[jn][0], bh[jn][1], bH + off);
                LDSM_X2(bl[jn][0], bl[jn][1], bL + off);
            }
#pragma unroll
            for (int mi = 0; mi < 4; mi++) {
                uint32_t off = (uint32_t)((wm + mi * 16 + (lane & 15)) * SPITCH +
                                          ks * 16 + ((lane >> 4) << 3)) * 2;
                uint32_t ah[4], al[4];
                LDSM_X4(ah[0], ah[1], ah[2], ah[3], aH + off);
                LDSM_X4(al[0], al[1], al[2], al[3], aL + off);
#pragma unroll
                for (int jn = 0; jn < 8; jn++) {
                    MMA16816(acc[mi][jn], ah, bh[jn][0], bh[jn][1]);
                    MMA16816(acc[mi][jn], ah, bl[jn][0], bl[jn][1]);
                    MMA16816(acc[mi][jn], al, bh[jn][0], bh[jn][1]);
                }
            }
        }
        __syncthreads();
        if (t + 2 < NCH) { stage(t + 2, (t + 2) % 3); CP_COMMIT(); }
    }

    int qr = lane >> 2, qc = (lane & 3) * 2;
#pragma unroll
    for (int mi = 0; mi < 4; mi++) {
#pragma unroll
        for (int jn = 0; jn < 8; jn++) {
            int row = m0 + wm + mi * 16 + qr;
            int col = n0 + wn + jn * 8 + qc;
            *(float2*)&C[(size_t)row * DIM + col] =
                make_float2(acc[mi][jn][0], acc[mi][jn][1]);
            *(float2*)&C[(size_t)(row + 8) * DIM + col] =
                make_float2(acc[mi][jn][2], acc[mi][jn][3]);
        }
    }
}

// ---------------- HMMA flash attention ----------------
#define PIT 136
#define FLASH_SMEM (6 * 128 * PIT * 2)

__global__ __launch_bounds__(256, 1)
void flash_mma(const __nv_bfloat16* __restrict__ Qhi, const __nv_bfloat16* __restrict__ Qlo,
               const __nv_bfloat16* __restrict__ Khi, const __nv_bfloat16* __restrict__ Klo,
               const __nv_bfloat16* __restrict__ Vhi, const __nv_bfloat16* __restrict__ Vlo,
               __nv_bfloat16* __restrict__ Oh, __nv_bfloat16* __restrict__ Ol)
{
    extern __shared__ __nv_bfloat16 smf[];
    __nv_bfloat16* sQh = smf;
    __nv_bfloat16* sQl = smf + 128 * PIT;
    __nv_bfloat16* sKh = smf + 2 * 128 * PIT;
    __nv_bfloat16* sKl = smf + 3 * 128 * PIT;
    __nv_bfloat16* sVh = smf + 4 * 128 * PIT;
    __nv_bfloat16* sVl = smf + 5 * 128 * PIT;

    int h  = blockIdx.y;
    int qt = (gridDim.x - 1) - blockIdx.x;
    int m0 = qt * 128;
    int kvh = h & 7;

    int tid = threadIdx.x, w = tid >> 5, lane = tid & 31;
    int gr = lane >> 2, qc = (lane & 3) * 2;

#pragma unroll
    for (int it = 0; it < 8; it++) {
        int idx = it * 256 + tid;
        int row = idx >> 4, c4 = idx & 15;
        *(uint4*)&sQh[row * PIT + c4 * 8] =
            *(const uint4*)(Qhi + (size_t)(m0 + row) * DIM + h * HD + c4 * 8);
        *(uint4*)&sQl[row * PIT + c4 * 8] =
            *(const uint4*)(Qlo + (size_t)(m0 + row) * DIM + h * HD + c4 * 8);
    }
    __syncthreads();

    float o[16][4];
#pragma unroll
    for (int j = 0; j < 16; j++)
#pragma unroll
        for (int c = 0; c < 4; c++) o[j][c] = 0.f;
    float mrow[2] = {-INFINITY, -INFINITY};
    float lrow[2] = {0.f, 0.f};
    const float scale = 0.08838834764831845f;

    for (int kt = 0; kt <= qt; kt++) {
        int n0 = kt * 128;
#pragma unroll
        for (int it = 0; it < 8; it++) {
            int idx = it * 256 + tid;
            int row = idx >> 4, c4 = idx & 15;
            size_t g = (size_t)(n0 + row) * KVD + kvh * HD + c4 * 8;
            uint32_t so = (uint32_t)(row * PIT + c4 * 8) * 2;
            cp16(smem_u32(sKh) + so, Khi + g);
            cp16(smem_u32(sKl) + so, Klo + g);
        }
        CP_COMMIT();
#pragma unroll
        for (int it = 0; it < 8; it++) {
            int idx = it * 256 + tid;
            int row = idx >> 4, c4 = idx & 15;
            size_t g = (size_t)(n0 + row) * KVD + kvh * HD + c4 * 8;
            uint32_t so = (uint32_t)(row * PIT + c4 * 8) * 2;
            cp16(smem_u32(sVh) + so, Vhi + g);
            cp16(smem_u32(sVl) + so, Vlo + g);
        }
        CP_COMMIT();

        CP_WAIT(1);
        __syncthreads();

        float s[16][4];
#pragma unroll
        for (int j = 0; j < 16; j++)
#pragma unroll
            for (int c = 0; c < 4; c++) s[j][c] = 0.f;

#pragma unroll
        for (int g = 0; g < 4; g++) {
            uint32_t a0h[4], a1h[4], a0l[4], a1l[4];
            uint32_t offA = (uint32_t)((w * 16 + (lane & 15)) * PIT + g * 32 +
                                       ((lane >> 4) << 3)) * 2;
            LDSM_X4(a0h[0], a0h[1], a0h[2], a0h[3], smem_u32(sQh) + offA);
            LDSM_X4(a1h[0], a1h[1], a1h[2], a1h[3], smem_u32(sQh) + offA + 32);
            LDSM_X4(a0l[0], a0l[1], a0l[2], a0l[3], smem_u32(sQl) + offA);
            LDSM_X4(a1l[0], a1l[1], a1l[2], a1l[3], smem_u32(sQl) + offA + 32);
#pragma unroll
            for (int jn = 0; jn < 16; jn++) {
                uint32_t offB = (uint32_t)((jn * 8 + (lane & 7)) * PIT + g * 32 +
                                           ((lane >> 3) << 3)) * 2;
                uint32_t bh0, bh1, bh2, bh3, bl0, bl1, bl2, bl3;
                LDSM_X4(bh0, bh1, bh2, bh3, smem_u32(sKh) + offB);
                LDSM_X4(bl0, bl1, bl2, bl3, smem_u32(sKl) + offB);
                MMA16816(s[jn], a0h, bh0, bh1);
                MMA16816(s[jn], a1h, bh2, bh3);
                MMA16816(s[jn], a0h, bl0, bl1);
                MMA16816(s[jn], a1h, bl2, bl3);
                MMA16816(s[jn], a0l, bh0, bh1);
                MMA16816(s[jn], a1l, bh2, bh3);
            }
        }

        if (kt == qt) {
#pragma unroll
            for (int jn = 0; jn < 16; jn++) {
                int c0 = jn * 8 + qc;
                int r0 = w * 16 + gr;
                s[jn][0] = (c0     > r0    ) ? -1e30f : s[jn][0] * scale;
                s[jn][1] = (c0 + 1 > r0    ) ? -1e30f : s[jn][1] * scale;
                s[jn][2] = (c0     > r0 + 8) ? -1e30f : s[jn][2] * scale;
                s[jn][3] = (c0 + 1 > r0 + 8) ? -1e30f : s[jn][3] * scale;
            }
        } else {
#pragma unroll
            for (int jn = 0; jn < 16; jn++)
#pragma unroll
                for (int c = 0; c < 4; c++) s[jn][c] *= scale;
        }

#pragma unroll
        for (int half = 0; half < 2; half++) {
            int b = half * 2;
            float tmax = s[0][b];
#pragma unroll
            for (int jn = 0; jn < 16; jn++)
                tmax = fmaxf(tmax, fmaxf(s[jn][b], s[jn][b + 1]));
            tmax = fmaxf(tmax, __shfl_xor_sync(0xffffffffu, tmax, 1));
            tmax = fmaxf(tmax, __shfl_xor_sync(0xffffffffu, tmax, 2));

            float mnew = fmaxf(mrow[half], tmax);
            float alpha = exp_fast(mrow[half] - mnew);
            mrow[half] = mnew;

            float rsum = 0.f;
#pragma unroll
            for (int jn = 0; jn < 16; jn++) {
                float p0 = exp_fast(s[jn][b] - mnew);
                float p1 = exp_fast(s[jn][b + 1] - mnew);
                s[jn][b] = p0;
                s[jn][b + 1] = p1;
                rsum += p0 + p1;
            }
            rsum += __shfl_xor_sync(0xffffffffu, rsum, 1);
            rsum += __shfl_xor_sync(0xffffffffu, rsum, 2);

            lrow[half] = lrow[half] * alpha + rsum;
#pragma unroll
            for (int jn = 0; jn < 16; jn++) {
                o[jn][b]     *= alpha;
                o[jn][b + 1] *= alpha;
            }
        }

        uint32_t ph[8][4], pl[8][4];
#pragma unroll
        for (int ks = 0; ks < 8; ks++) {
#pragma unroll
            for (int q = 0; q < 4; q++) {
                int jn = 2 * ks + (q >> 1);
                int c  = (q & 1) * 2;
                float f0 = s[jn][c], f1 = s[jn][c + 1];
                uint32_t hp = pack_bf16x2(f0, f1);
                ph[ks][q] = hp;
                float h0 = __uint_as_float(hp << 16);
                float h1 = __uint_as_float(hp & 0xffff0000u);
                pl[ks][q] = pack_bf16x2(f0 - h0, f1 - h1);
            }
        }

        CP_WAIT(0);
        __syncthreads();

#pragma unroll
        for (int ks = 0; ks < 8; ks++) {
#pragma unroll
            for (int jp = 0; jp < 8; jp++) {
                uint32_t offV = (uint32_t)((ks * 16 + (lane & 7) + ((lane >> 3) & 1) * 8) * PIT +
                                           jp * 16 + ((lane >> 4) << 3)) * 2;
                uint32_t vh0, vh1, vh2, vh3, vl0, vl1, vl2, vl3;
                LDSM_X4_T(vh0, vh1, vh2, vh3, smem_u32(sVh) + offV);
                LDSM_X4_T(vl0, vl1, vl2, vl3, smem_u32(sVl) + offV);
                MMA16816(o[2 * jp],     ph[ks], vh0, vh1);
                MMA16816(o[2 * jp + 1], ph[ks], vh2, vh3);
                MMA16816(o[2 * jp],     ph[ks], vl0, vl1);
                MMA16816(o[2 * jp + 1], ph[ks], vl2, vl3);
                MMA16816(o[2 * jp],     pl[ks], vh0, vh1);
                MMA16816(o[2 * jp + 1], pl[ks], vh2, vh3);
            }
        }
        __syncthreads();
    }

    // ---- epilogue: write att bf16 hi/lo directly ----
    float inv0 = 1.f / lrow[0], inv1 = 1.f / lrow[1];
    int row0 = m0 + w * 16 + gr;
#pragma unroll
    for (int jn = 0; jn < 16; jn++) {
        int col = h * HD + jn * 8 + qc;
        float v0 = o[jn][0] * inv0, v1 = o[jn][1] * inv0;
        float v2 = o[jn][2] * inv1, v3 = o[jn][3] * inv1;
        uint32_t hw0 = pack_bf16x2(v0, v1);
        uint32_t lw0 = pack_bf16x2(v0 - __uint_as_float(hw0 << 16),
                                   v1 - __uint_as_float(hw0 & 0xffff0000u));
        uint32_t hw1 = pack_bf16x2(v2, v3);
        uint32_t lw1 = pack_bf16x2(v2 - __uint_as_float(hw1 << 16),
                                   v3 - __uint_as_float(hw1 & 0xffff0000u));
        *(uint32_t*)&Oh[(size_t)row0 * DIM + col]       = hw0;
        *(uint32_t*)&Ol[(size_t)row0 * DIM + col]       = lw0;
        *(uint32_t*)&Oh[(size_t)(row0 + 8) * DIM + col] = hw1;
        *(uint32_t*)&Ol[(size_t)(row0 + 8) * DIM + col] = lw1;
    }
}

// ---------------- launch ----------------
extern "C" void kernel_launch(void* const* d_in, const int* in_sizes, int n_in,
                              void* d_out, int out_size)
{
    const float* x  = (const float*)d_in[0];
    const float* wq = (const float*)d_in[1];
    const float* wk = (const float*)d_in[2];
    const float* wv = (const float*)d_in[3];
    const float* wo = (const float*)d_in[4];
    const float* fc = (const float*)d_in[5];
    const float* fs = (const float*)d_in[6];
    float* out = (float*)d_out;

    __nv_bfloat16 *pxhi, *pxlo, *pahi, *palo;
    __nv_bfloat16 *pqh, *pql, *pkh, *pkl, *pvh, *pvl;
    __nv_bfloat16 *pwqh, *pwql, *pwkh, *pwkl, *pwvh, *pwvl, *pwoh, *pwol;
    cudaGetSymbolAddress((void**)&pxhi, g_xhi);
    cudaGetSymbolAddress((void**)&pxlo, g_xlo);
    cudaGetSymbolAddress((void**)&pahi, g_atthi);
    cudaGetSymbolAddress((void**)&palo, g_attlo);
    cudaGetSymbolAddress((void**)&pqh,  g_qhi);
    cudaGetSymbolAddress((void**)&pql,  g_qlo);
    cudaGetSymbolAddress((void**)&pkh,  g_khi);
    cudaGetSymbolAddress((void**)&pkl,  g_klo);
    cudaGetSymbolAddress((void**)&pvh,  g_vhi);
    cudaGetSymbolAddress((void**)&pvl,  g_vlo);
    cudaGetSymbolAddress((void**)&pwqh, g_wqT_hi);
    cudaGetSymbolAddress((void**)&pwql, g_wqT_lo);
    cudaGetSymbolAddress((void**)&pwkh, g_wkT_hi);
    cudaGetSymbolAddress((void**)&pwkl, g_wkT_lo);
    cudaGetSymbolAddress((void**)&pwvh, g_wvT_hi);
    cudaGetSymbolAddress((void**)&pwvl, g_wvT_lo);
    cudaGetSymbolAddress((void**)&pwoh, g_woT_hi);
    cudaGetSymbolAddress((void**)&pwol, g_woT_lo);

    static bool attr_set = false;
    if (!attr_set) {
        cudaFuncSetAttribute(flash_mma, cudaFuncAttributeMaxDynamicSharedMemorySize,
                             FLASH_SMEM);
        cudaFuncSetAttribute(gemm_qkv, cudaFuncAttributeMaxDynamicSharedMemorySize,
                             QKV_SMEM);
        cudaFuncSetAttribute(gemm_out, cudaFuncAttributeMaxDynamicSharedMemorySize,
                             QKV_SMEM);
        attr_set = true;
    }

    // ---- conversions ----
    transpose_split<<<dim3(DIM / 32, DIM / 32), 256>>>(wq, pwqh, pwql, DIM, DIM);
    transpose_split<<<dim3(KVD / 32, DIM / 32), 256>>>(wk, pwkh, pwkl, DIM, KVD);
    transpose_split<<<dim3(KVD / 32, DIM / 32), 256>>>(wv, pwvh, pwvl, DIM, KVD);
    transpose_split<<<dim3(DIM / 32, DIM / 32), 256>>>(wo, pwoh, pwol, DIM, DIM);
    split_rows<<<(SQ * DIM) / 256, 256>>>(x, pxhi, pxlo);

    // ---- fused QKV projection + RoPE + bf16 split ----
    gemm_qkv<<<dim3(24, SQ / 128), 256, QKV_SMEM>>>(
        pxhi, pxlo, pwqh, pwql, pwkh, pwkl, pwvh, pwvl,
        pqh, pql, pkh, pkl, pvh, pvl, fc, fs);

    // ---- fused attention (writes att hi/lo) ----
    flash_mma<<<dim3(SQ / 128, NH), 256, FLASH_SMEM>>>(pqh, pql, pkh, pkl, pvh, pvl,
                                                       pahi, palo);

    // ---- output projection ----
    gemm_out<<<dim3(DIM / 256, SQ / 128), 256, QKV_SMEM>>>(pahi, palo, pwoh, pwol, out);
}